// round 2
// baseline (speedup 1.0000x reference)
#include <cuda_runtime.h>
#include <math.h>

#define B_ 16
#define C_ 512
#define N_ 4096
#define M_ 64

// ---- scratch (static device globals; no runtime allocation) ----
__device__ float g_Q[B_*M_*N_];      // 16 MB, Q then Qn (in place)
__device__ float g_K[B_*M_*N_];      // 16 MB, K then Kn (in place)
__device__ float g_KX[B_*M_*C_];     // 2 MB
__device__ float g_mat[B_*M_*C_];    // 2 MB
__device__ float g_Knsum[B_*M_];
__device__ float g_xsum[B_*C_];
__device__ float g_Vsum[B_*C_];
__device__ float g_tailor[B_*N_];

// ---------------------------------------------------------------
// block-level sum reduction
__device__ __forceinline__ float blk_reduce(float v) {
    __shared__ float s[32];
    int lane = threadIdx.x & 31, w = threadIdx.x >> 5;
#pragma unroll
    for (int o = 16; o; o >>= 1) v += __shfl_xor_sync(0xffffffffu, v, o);
    if (lane == 0) s[w] = v;
    __syncthreads();
    int nw = blockDim.x >> 5;
    v = (threadIdx.x < nw) ? s[threadIdx.x] : 0.f;
    if (w == 0) {
#pragma unroll
        for (int o = 16; o; o >>= 1) v += __shfl_xor_sync(0xffffffffu, v, o);
    }
    return v;  // valid in thread 0
}

// ---------------------------------------------------------------
// xsum[b][c] = sum_n x[b][c][n];  grid (512, 16), 128 thr
__global__ void rowsum_x(const float* __restrict__ x) {
    int row = blockIdx.y * gridDim.x + blockIdx.x;   // b*512 + c
    const float* p = x + (size_t)row * N_;
    float s = 0.f;
    for (int i = threadIdx.x; i < N_; i += blockDim.x) s += p[i];
    s = blk_reduce(s);
    if (threadIdx.x == 0) g_xsum[row] = s;
}

// Knsum[b][m] = sum_n Kn[b][m][n];  grid (64, 16), 128 thr (after norm)
__global__ void rowsum_K() {
    int row = blockIdx.y * gridDim.x + blockIdx.x;   // b*64 + m
    const float* p = g_K + (size_t)row * N_;
    float s = 0.f;
    for (int i = threadIdx.x; i < N_; i += blockDim.x) s += p[i];
    s = blk_reduce(s);
    if (threadIdx.x == 0) g_Knsum[row] = s;
}

// ---------------------------------------------------------------
// Q/K projection: [128(m: 64q + 64k) x 128(n)] tile, K=512.  grid (32, 16), 256 thr
__global__ void qk_gemm(const float* __restrict__ x, const float* __restrict__ Wq,
                        const float* __restrict__ bq, const float* __restrict__ Wk,
                        const float* __restrict__ bk) {
    __shared__ float As[16][132];  // As[k][m]
    __shared__ float Bs[16][132];  // Bs[k][n]
    const int b  = blockIdx.y;
    const int n0 = blockIdx.x * 128;
    const int t  = threadIdx.x;
    const int tm = t >> 4;   // 0..15 (m base)
    const int tn = t & 15;   // 0..15 (n base)
    const float* xb = x + (size_t)b * C_ * N_;
    float acc[8][8];
#pragma unroll
    for (int i = 0; i < 8; i++)
#pragma unroll
        for (int j = 0; j < 8; j++) acc[i][j] = 0.f;

    for (int k0 = 0; k0 < C_; k0 += 16) {
#pragma unroll
        for (int i = 0; i < 8; i++) {
            int idx = t + i * 256;          // 2048 elems of A
            int m = idx >> 4, k = idx & 15;
            As[k][m] = (m < 64) ? Wq[m * C_ + k0 + k] : Wk[(m - 64) * C_ + k0 + k];
        }
#pragma unroll
        for (int i = 0; i < 8; i++) {
            int idx = t + i * 256;          // 2048 elems of B
            int k = idx >> 7, n = idx & 127;
            Bs[k][n] = xb[(size_t)(k0 + k) * N_ + n0 + n];
        }
        __syncthreads();
#pragma unroll
        for (int k = 0; k < 16; k++) {
            float a[8], bb[8];
#pragma unroll
            for (int i = 0; i < 8; i++) a[i]  = As[k][tm + 16 * i];
#pragma unroll
            for (int j = 0; j < 8; j++) bb[j] = Bs[k][tn + 16 * j];
#pragma unroll
            for (int i = 0; i < 8; i++)
#pragma unroll
                for (int j = 0; j < 8; j++) acc[i][j] = fmaf(a[i], bb[j], acc[i][j]);
        }
        __syncthreads();
    }
#pragma unroll
    for (int i = 0; i < 8; i++) {
        int m = tm + 16 * i;
        float bias; float* dst;
        if (m < 64) { bias = bq[m];      dst = g_Q + ((size_t)b * M_ + m) * N_; }
        else        { bias = bk[m - 64]; dst = g_K + ((size_t)b * M_ + (m - 64)) * N_; }
#pragma unroll
        for (int j = 0; j < 8; j++) dst[n0 + tn + 16 * j] = acc[i][j] + bias;
    }
}

// ---------------------------------------------------------------
// per-column L2 normalize (channel dim, 64), in place.  grid (16, 16), 256 thr
__global__ void norm_qk() {
    int b = blockIdx.y;
    int n = blockIdx.x * 256 + threadIdx.x;
    float* Qb = g_Q + (size_t)b * M_ * N_;
    float* Kb = g_K + (size_t)b * M_ * N_;
    float sq = 0.f, sk = 0.f;
#pragma unroll 8
    for (int m = 0; m < 64; m++) {
        float q = Qb[(size_t)m * N_ + n]; sq = fmaf(q, q, sq);
        float k = Kb[(size_t)m * N_ + n]; sk = fmaf(k, k, sk);
    }
    float iq = 1.f / fmaxf(sqrtf(sq), 1e-6f);
    float ik = 1.f / fmaxf(sqrtf(sk), 1e-6f);
#pragma unroll 8
    for (int m = 0; m < 64; m++) {
        Qb[(size_t)m * N_ + n] *= iq;
        Kb[(size_t)m * N_ + n] *= ik;
    }
}

// ---------------------------------------------------------------
// tailor[b][n] = 1 / max(N + sum_m Qn[m][n]*Knsum[m], 1e-6).  grid (16, 16), 256 thr
__global__ void tailor_kernel() {
    __shared__ float ks[64];
    int b = blockIdx.y;
    if (threadIdx.x < 64) ks[threadIdx.x] = g_Knsum[b * 64 + threadIdx.x];
    __syncthreads();
    int n = blockIdx.x * 256 + threadIdx.x;
    const float* Qb = g_Q + (size_t)b * M_ * N_;
    float d = (float)N_;
#pragma unroll 8
    for (int m = 0; m < 64; m++) d = fmaf(Qb[(size_t)m * N_ + n], ks[m], d);
    g_tailor[b * N_ + n] = 1.f / fmaxf(d, 1e-6f);
}

// ---------------------------------------------------------------
// KX[b][m][c] = sum_n Kn[b][m][n] * x[b][c][n].  tile 64x64, K=4096. grid (8, 16), 256 thr
__global__ void kx_gemm(const float* __restrict__ x) {
    __shared__ float As[64][65];
    __shared__ float Bs[64][65];
    int b  = blockIdx.y;
    int c0 = blockIdx.x * 64;
    const float* A  = g_K + (size_t)b * M_ * N_;
    const float* Bm = x + (size_t)b * C_ * N_ + (size_t)c0 * N_;
    int t = threadIdx.x;
    int tm = t >> 4, tc = t & 15;
    float acc[4][4] = {};
    for (int k0 = 0; k0 < N_; k0 += 64) {
#pragma unroll
        for (int i = 0; i < 16; i++) {
            int idx = t + i * 256;
            int r = idx >> 6, kk = idx & 63;
            As[r][kk] = A [(size_t)r * N_ + k0 + kk];
            Bs[r][kk] = Bm[(size_t)r * N_ + k0 + kk];
        }
        __syncthreads();
#pragma unroll
        for (int kk = 0; kk < 64; kk++) {
            float a[4], bb[4];
#pragma unroll
            for (int i = 0; i < 4; i++) a[i]  = As[tm + 16 * i][kk];
#pragma unroll
            for (int j = 0; j < 4; j++) bb[j] = Bs[tc + 16 * j][kk];
#pragma unroll
            for (int i = 0; i < 4; i++)
#pragma unroll
                for (int j = 0; j < 4; j++) acc[i][j] = fmaf(a[i], bb[j], acc[i][j]);
        }
        __syncthreads();
    }
    float* Cp = g_KX + (size_t)b * M_ * C_;
#pragma unroll
    for (int i = 0; i < 4; i++)
#pragma unroll
        for (int j = 0; j < 4; j++)
            Cp[(size_t)(tm + 16 * i) * C_ + c0 + tc + 16 * j] = acc[i][j];
}

// ---------------------------------------------------------------
// mat[b][m][c] = sum_{c'} KX[b][m][c'] * Wv[c][c'] + bv[c]*Knsum[b][m]. grid (8,16), 256 thr
__global__ void mat_gemm(const float* __restrict__ Wv, const float* __restrict__ bv) {
    __shared__ float As[64][65];
    __shared__ float Bs[64][65];
    int b  = blockIdx.y;
    int c0 = blockIdx.x * 64;
    const float* A  = g_KX + (size_t)b * M_ * C_;
    const float* Bm = Wv + (size_t)c0 * C_;
    int t = threadIdx.x;
    int tm = t >> 4, tc = t & 15;
    float acc[4][4] = {};
    for (int k0 = 0; k0 < C_; k0 += 64) {
#pragma unroll
        for (int i = 0; i < 16; i++) {
            int idx = t + i * 256;
            int r = idx >> 6, kk = idx & 63;
            As[r][kk] = A [(size_t)r * C_ + k0 + kk];
            Bs[r][kk] = Bm[(size_t)r * C_ + k0 + kk];
        }
        __syncthreads();
#pragma unroll
        for (int kk = 0; kk < 64; kk++) {
            float a[4], bb[4];
#pragma unroll
            for (int i = 0; i < 4; i++) a[i]  = As[tm + 16 * i][kk];
#pragma unroll
            for (int j = 0; j < 4; j++) bb[j] = Bs[tc + 16 * j][kk];
#pragma unroll
            for (int i = 0; i < 4; i++)
#pragma unroll
                for (int j = 0; j < 4; j++) acc[i][j] = fmaf(a[i], bb[j], acc[i][j]);
        }
        __syncthreads();
    }
    float* Cp = g_mat + (size_t)b * M_ * C_;
#pragma unroll
    for (int i = 0; i < 4; i++) {
        int m = tm + 16 * i;
        float kn = g_Knsum[b * 64 + m];
#pragma unroll
        for (int j = 0; j < 4; j++) {
            int c = c0 + tc + 16 * j;
            Cp[(size_t)m * C_ + c] = acc[i][j] + bv[c] * kn;
        }
    }
}

// ---------------------------------------------------------------
// Vsum[b][c] = Wv[c,:].xsum[b,:] + N*bv[c].  grid (128, 16), 128 thr (warp per c)
__global__ void vsum_kernel(const float* __restrict__ Wv, const float* __restrict__ bv) {
    int b = blockIdx.y;
    int c = blockIdx.x * 4 + (threadIdx.x >> 5);
    int lane = threadIdx.x & 31;
    const float* w  = Wv + (size_t)c * C_;
    const float* xs = g_xsum + b * C_;
    float s = 0.f;
    for (int i = lane; i < C_; i += 32) s = fmaf(w[i], xs[i], s);
#pragma unroll
    for (int o = 16; o; o >>= 1) s += __shfl_xor_sync(0xffffffffu, s, o);
    if (lane == 0) g_Vsum[b * C_ + c] = s + (float)N_ * bv[c];
}

// ---------------------------------------------------------------
// out[b][c][n] = nan_to_num(gamma * tailor[n] * (Vsum[c] + sum_m Qn[m][n]*mat[m][c]))
// grid (64, 8, 16), 256 thr; tile 64c x 64n, K=64
__global__ void final_kernel(float* __restrict__ out, const float* __restrict__ gamma) {
    __shared__ float Ms[64][64];   // Ms[m][cc]
    __shared__ float Qs[64][64];   // Qs[m][nn]
    int b  = blockIdx.z;
    int c0 = blockIdx.y * 64;
    int n0 = blockIdx.x * 64;
    const float* mat = g_mat + (size_t)b * M_ * C_;
    const float* Qb  = g_Q + (size_t)b * M_ * N_;
    int t = threadIdx.x;
#pragma unroll
    for (int i = 0; i < 16; i++) {
        int idx = t + i * 256;
        int m = idx >> 6, cc = idx & 63;
        Ms[m][cc] = mat[(size_t)m * C_ + c0 + cc];
        Qs[m][cc] = Qb [(size_t)m * N_ + n0 + cc];
    }
    __syncthreads();
    int tc = t >> 4, tn = t & 15;
    float acc[4][4] = {};
#pragma unroll
    for (int m = 0; m < 64; m++) {
        float a[4], bb[4];
#pragma unroll
        for (int i = 0; i < 4; i++) a[i]  = Ms[m][tc + 16 * i];
#pragma unroll
        for (int j = 0; j < 4; j++) bb[j] = Qs[m][tn + 16 * j];
#pragma unroll
        for (int i = 0; i < 4; i++)
#pragma unroll
            for (int j = 0; j < 4; j++) acc[i][j] = fmaf(a[i], bb[j], acc[i][j]);
    }
    float g = gamma[0];
    const float* vs = g_Vsum + b * C_;
    const float* tl = g_tailor + (size_t)b * N_;
#pragma unroll
    for (int i = 0; i < 4; i++) {
        int c = c0 + tc + 16 * i;
        float vsum = vs[c];
        float* orow = out + ((size_t)b * C_ + c) * N_;
#pragma unroll
        for (int j = 0; j < 4; j++) {
            int n = n0 + tn + 16 * j;
            float val = g * tl[n] * (vsum + acc[i][j]);
            if (isnan(val)) val = 0.f;
            else if (isinf(val)) val = val > 0.f ? 1.f : -1.f;
            orow[n] = val;
        }
    }
}

// ---------------------------------------------------------------
extern "C" void kernel_launch(void* const* d_in, const int* in_sizes, int n_in,
                              void* d_out, int out_size) {
    const float* x     = (const float*)d_in[0];
    const float* Wq    = (const float*)d_in[1];
    const float* bq    = (const float*)d_in[2];
    const float* Wk    = (const float*)d_in[3];
    const float* bk    = (const float*)d_in[4];
    const float* Wv    = (const float*)d_in[5];
    const float* bv    = (const float*)d_in[6];
    const float* gamma = (const float*)d_in[7];
    float* out = (float*)d_out;

    rowsum_x    <<<dim3(512, 16), 128>>>(x);
    qk_gemm     <<<dim3(32, 16), 256>>>(x, Wq, bq, Wk, bk);
    norm_qk     <<<dim3(16, 16), 256>>>();
    rowsum_K    <<<dim3(64, 16), 128>>>();
    tailor_kernel<<<dim3(16, 16), 256>>>();
    kx_gemm     <<<dim3(8, 16), 256>>>(x);
    mat_gemm    <<<dim3(8, 16), 256>>>(Wv, bv);
    vsum_kernel <<<dim3(128, 16), 128>>>(Wv, bv);
    final_kernel<<<dim3(64, 8, 16), 256>>>(out, gamma);
}

// round 4
// speedup vs baseline: 2.1847x; 2.1847x over previous
#include <cuda_runtime.h>
#include <cuda_bf16.h>
#include <cstdint>
#include <math.h>

#define B_ 16
#define C_ 512
#define N_ 4096
#define M_ 64

// ---------------- scratch (static device globals) ----------------
__device__ __align__(128) float g_QnT[B_*N_*M_];      // [b][n][m]
__device__ __align__(128) float g_Kn [B_*M_*N_];      // [b][m][n]
__device__ __align__(128) float g_KXp[4][B_*M_*C_];   // k-split partials [ks][b][m][c]
__device__ __align__(128) float g_KXs[B_*M_*C_];      // summed
__device__ __align__(128) float g_matT[B_*C_*M_];     // [b][c][m]
__device__ __align__(128) float g_Knsum[B_*M_];
__device__ __align__(128) float g_xsum[B_*C_];
__device__ __align__(128) float g_Vsum[B_*C_];
__device__ __align__(128) float g_tailor[B_*N_];

// ---------------- bf16 split helpers ----------------
__device__ __forceinline__ uint32_t bpk(float a, float b) {
    __nv_bfloat162 t = __floats2bfloat162_rn(a, b);
    return *reinterpret_cast<uint32_t*>(&t);
}
__device__ __forceinline__ void split4(float4 v, uint2& h, uint2& l) {
    float hx = __bfloat162float(__float2bfloat16_rn(v.x));
    float hy = __bfloat162float(__float2bfloat16_rn(v.y));
    float hz = __bfloat162float(__float2bfloat16_rn(v.z));
    float hw = __bfloat162float(__float2bfloat16_rn(v.w));
    h.x = bpk(hx, hy);          h.y = bpk(hz, hw);
    l.x = bpk(v.x - hx, v.y - hy); l.y = bpk(v.z - hz, v.w - hw);
}
__device__ __forceinline__ void split2(float a, float b, uint32_t& h, uint32_t& l) {
    float ha = __bfloat162float(__float2bfloat16_rn(a));
    float hb = __bfloat162float(__float2bfloat16_rn(b));
    h = bpk(ha, hb); l = bpk(a - ha, b - hb);
}

// ---------------- warp mma helpers ----------------
__device__ __forceinline__ void mma_bf16(float c[4], const uint32_t a[4], const uint32_t b[2]) {
    asm volatile("mma.sync.aligned.m16n8k16.row.col.f32.bf16.bf16.f32 "
        "{%0,%1,%2,%3}, {%4,%5,%6,%7}, {%8,%9}, {%0,%1,%2,%3};"
        : "+f"(c[0]), "+f"(c[1]), "+f"(c[2]), "+f"(c[3])
        : "r"(a[0]), "r"(a[1]), "r"(a[2]), "r"(a[3]), "r"(b[0]), "r"(b[1]));
}
__device__ __forceinline__ void ldAf(uint32_t a[4], const char* base, int pitch,
                                     int row, int kc, int r, int kq) {
    const __nv_bfloat16* p = (const __nv_bfloat16*)base;
    a[0] = *(const uint32_t*)(p + (row + r    ) * pitch + kc + kq);
    a[1] = *(const uint32_t*)(p + (row + r + 8) * pitch + kc + kq);
    a[2] = *(const uint32_t*)(p + (row + r    ) * pitch + kc + kq + 8);
    a[3] = *(const uint32_t*)(p + (row + r + 8) * pitch + kc + kq + 8);
}
__device__ __forceinline__ void ldBf(uint32_t bb[2], const char* base, int pitch,
                                     int row, int kc, int r, int kq) {
    const __nv_bfloat16* p = (const __nv_bfloat16*)base;
    bb[0] = *(const uint32_t*)(p + (row + r) * pitch + kc + kq);
    bb[1] = *(const uint32_t*)(p + (row + r) * pitch + kc + kq + 8);
}
__device__ __forceinline__ float fixv(float v) {
    if (isnan(v)) return 0.f;
    if (isinf(v)) return v > 0.f ? 1.f : -1.f;
    return v;
}

// =====================================================================
// qk_mma: D[128m(64q|64k)][128n] = Wqk @ x, K=512. grid(32,16), 256 thr
// smem layout (bytes):
//  ops:  Ah 0 (10240) Al 10240 Bh 20480 Bl 30720  Ss 40960 (16896)
//  epi:  Cs 0 (128*133*4 = 68096)
//  tail: bias 68096, inq 68608, ink 69120, total 69632
// =====================================================================
#define QK_AH 0
#define QK_AL 10240
#define QK_BH 20480
#define QK_BL 30720
#define QK_SS 40960
#define QK_CS 0
#define QK_BIAS 68096
#define QK_INQ 68608
#define QK_INK 69120
#define QK_BYTES 69632

__global__ __launch_bounds__(256, 1) void qk_mma(
    const float* __restrict__ x,  const float* __restrict__ Wq,
    const float* __restrict__ bq, const float* __restrict__ Wk,
    const float* __restrict__ bk) {
    extern __shared__ __align__(16) char sm[];
    const int t = threadIdx.x, lane = t & 31, wid = t >> 5;
    const int b = blockIdx.y, n0 = blockIdx.x * 128;
    const float* xb = x + (size_t)b * C_ * N_;
    float* bias = (float*)(sm + QK_BIAS);
    float* inq  = (float*)(sm + QK_INQ);
    float* ink  = (float*)(sm + QK_INK);
    if (t < 128) bias[t] = (t < 64) ? bq[t] : bk[t - 64];

    const int m0 = (wid >> 2) * 64, nw = (wid & 3) * 32;
    const int r = lane >> 2, kq = (lane & 3) * 2;
    float acc[4][4][4] = {};
    float* Ss = (float*)(sm + QK_SS);
    __nv_bfloat16* Ah = (__nv_bfloat16*)(sm + QK_AH);
    __nv_bfloat16* Al = (__nv_bfloat16*)(sm + QK_AL);
    __nv_bfloat16* Bh = (__nv_bfloat16*)(sm + QK_BH);
    __nv_bfloat16* Bl = (__nv_bfloat16*)(sm + QK_BL);

    for (int p = 0; p < 16; ++p) {
        const int k0 = p * 32;
        // A: Wqk rows (m), 32 k
#pragma unroll
        for (int i = 0; i < 4; i++) {
            int idx = t + i * 256, row = idx >> 3, g = idx & 7;
            float4 v = (row < 64) ? *(const float4*)(Wq + (size_t)row * C_ + k0 + 4*g)
                                  : *(const float4*)(Wk + (size_t)(row - 64) * C_ + k0 + 4*g);
            uint2 h, l; split4(v, h, l);
            *(uint2*)(Ah + row * 40 + 4*g) = h;
            *(uint2*)(Al + row * 40 + 4*g) = l;
        }
        // x -> staging (coalesced)
#pragma unroll
        for (int i = 0; i < 4; i++) {
            int idx = t + i * 256, kk = idx >> 5, g = idx & 31;
            *(float4*)(Ss + kk * 132 + 4*g) =
                *(const float4*)(xb + (size_t)(k0 + kk) * N_ + n0 + 4*g);
        }
        __syncthreads();
        // transpose staging -> B rows (n)
        {
            int n = t & 127, kh = (t >> 7) * 16;
#pragma unroll
            for (int j = 0; j < 16; j += 2) {
                float v0 = Ss[(kh + j) * 132 + n], v1 = Ss[(kh + j + 1) * 132 + n];
                uint32_t h, l; split2(v0, v1, h, l);
                *(uint32_t*)(Bh + n * 40 + kh + j) = h;
                *(uint32_t*)(Bl + n * 40 + kh + j) = l;
            }
        }
        __syncthreads();
#pragma unroll
        for (int kc = 0; kc < 32; kc += 16) {
            uint32_t ah[4][4], al[4][4], bh[4][2], bl[4][2];
#pragma unroll
            for (int mf = 0; mf < 4; mf++) {
                ldAf(ah[mf], (char*)Ah, 40, m0 + mf*16, kc, r, kq);
                ldAf(al[mf], (char*)Al, 40, m0 + mf*16, kc, r, kq);
            }
#pragma unroll
            for (int nf = 0; nf < 4; nf++) {
                ldBf(bh[nf], (char*)Bh, 40, nw + nf*8, kc, r, kq);
                ldBf(bl[nf], (char*)Bl, 40, nw + nf*8, kc, r, kq);
            }
#pragma unroll
            for (int mf = 0; mf < 4; mf++)
#pragma unroll
                for (int nf = 0; nf < 4; nf++) {
                    mma_bf16(acc[mf][nf], ah[mf], bh[nf]);
                    mma_bf16(acc[mf][nf], al[mf], bh[nf]);
                    mma_bf16(acc[mf][nf], ah[mf], bl[nf]);
                }
        }
        __syncthreads();
    }
    // ---- epilogue: stage to Cs (fp32, pitch 133) with bias ----
    float* Cs = (float*)(sm + QK_CS);
#pragma unroll
    for (int mf = 0; mf < 4; mf++) {
        int mA = m0 + mf*16 + r, mB = mA + 8;
        float bA = bias[mA], bB = bias[mB];
#pragma unroll
        for (int nf = 0; nf < 4; nf++) {
            int n = nw + nf*8 + kq;
            Cs[mA * 133 + n    ] = acc[mf][nf][0] + bA;
            Cs[mA * 133 + n + 1] = acc[mf][nf][1] + bA;
            Cs[mB * 133 + n    ] = acc[mf][nf][2] + bB;
            Cs[mB * 133 + n + 1] = acc[mf][nf][3] + bB;
        }
    }
    __syncthreads();
    // ---- per-column L2 norms ----
    {
        int n = t & 127, part = t >> 7, base = part * 64;
        float s = 0.f;
#pragma unroll 8
        for (int m = 0; m < 64; m++) {
            float v = Cs[(base + m) * 133 + n]; s = fmaf(v, v, s);
        }
        float inv = 1.f / fmaxf(sqrtf(s), 1e-6f);
        if (part == 0) inq[n] = inv; else ink[n] = inv;
    }
    __syncthreads();
    // ---- write Kn[m][n] (coalesced) ----
#pragma unroll
    for (int i = 0; i < 8; i++) {
        int idx = t + i * 256, m = idx >> 5, g = idx & 31;
        float4 v;
        v.x = Cs[(64 + m) * 133 + 4*g + 0] * ink[4*g + 0];
        v.y = Cs[(64 + m) * 133 + 4*g + 1] * ink[4*g + 1];
        v.z = Cs[(64 + m) * 133 + 4*g + 2] * ink[4*g + 2];
        v.w = Cs[(64 + m) * 133 + 4*g + 3] * ink[4*g + 3];
        *(float4*)(g_Kn + ((size_t)b * M_ + m) * N_ + n0 + 4*g) = v;
    }
    // ---- write QnT[n][m] ----
#pragma unroll
    for (int i = 0; i < 8; i++) {
        int idx = t + i * 256, n = idx >> 4, g = idx & 15;
        float iq = inq[n];
        float4 v;
        v.x = Cs[(4*g + 0) * 133 + n] * iq;
        v.y = Cs[(4*g + 1) * 133 + n] * iq;
        v.z = Cs[(4*g + 2) * 133 + n] * iq;
        v.w = Cs[(4*g + 3) * 133 + n] * iq;
        *(float4*)(g_QnT + ((size_t)b * N_ + n0 + n) * M_ + 4*g) = v;
    }
}

// =====================================================================
// kx_mma: D[64m][128c] = Kn @ x^T over k-slice of 1024.
// grid (4 c-tiles, 16 b, 4 ksplit), 256 thr. static smem.
// ops: Ah 0 (5120) Al 5120 Bh 10240 (10240) Bl 20480 -> 30720
// Cs: 0 (64*132*4 = 33792)
// =====================================================================
#define KX_AH 0
#define KX_AL 5120
#define KX_BH 10240
#define KX_BL 20480
#define KX_CS 0
#define KX_BYTES 33792

__global__ __launch_bounds__(256, 1) void kx_mma(const float* __restrict__ x) {
    __shared__ __align__(16) char sm[KX_BYTES];
    const int t = threadIdx.x, lane = t & 31, wid = t >> 5;
    const int b = blockIdx.y, c0 = blockIdx.x * 128, ks = blockIdx.z;
    const float* Kb = g_Kn + (size_t)b * M_ * N_;
    const float* xb = x + (size_t)b * C_ * N_ + (size_t)c0 * N_;
    const int m0 = (wid >> 2) * 32, cw = (wid & 3) * 32;
    const int r = lane >> 5 ? 0 : (lane >> 2), kq = (lane & 3) * 2;
    __nv_bfloat16* Ah = (__nv_bfloat16*)(sm + KX_AH);
    __nv_bfloat16* Al = (__nv_bfloat16*)(sm + KX_AL);
    __nv_bfloat16* Bh = (__nv_bfloat16*)(sm + KX_BH);
    __nv_bfloat16* Bl = (__nv_bfloat16*)(sm + KX_BL);
    float acc[2][4][4] = {};

    for (int p = 0; p < 32; ++p) {
        const int k0 = ks * 1024 + p * 32;
#pragma unroll
        for (int i = 0; i < 2; i++) {       // A: Kn rows (m)
            int idx = t + i * 256, row = idx >> 3, g = idx & 7;
            float4 v = *(const float4*)(Kb + (size_t)row * N_ + k0 + 4*g);
            uint2 h, l; split4(v, h, l);
            *(uint2*)(Ah + row * 40 + 4*g) = h;
            *(uint2*)(Al + row * 40 + 4*g) = l;
        }
#pragma unroll
        for (int i = 0; i < 4; i++) {       // B: x rows (c)
            int idx = t + i * 256, row = idx >> 3, g = idx & 7;
            float4 v = *(const float4*)(xb + (size_t)row * N_ + k0 + 4*g);
            uint2 h, l; split4(v, h, l);
            *(uint2*)(Bh + row * 40 + 4*g) = h;
            *(uint2*)(Bl + row * 40 + 4*g) = l;
        }
        __syncthreads();
#pragma unroll
        for (int kc = 0; kc < 32; kc += 16) {
            uint32_t ah[2][4], al[2][4], bh[4][2], bl[4][2];
#pragma unroll
            for (int mf = 0; mf < 2; mf++) {
                ldAf(ah[mf], (char*)Ah, 40, m0 + mf*16, kc, r, kq);
                ldAf(al[mf], (char*)Al, 40, m0 + mf*16, kc, r, kq);
            }
#pragma unroll
            for (int nf = 0; nf < 4; nf++) {
                ldBf(bh[nf], (char*)Bh, 40, cw + nf*8, kc, r, kq);
                ldBf(bl[nf], (char*)Bl, 40, cw + nf*8, kc, r, kq);
            }
#pragma unroll
            for (int mf = 0; mf < 2; mf++)
#pragma unroll
                for (int nf = 0; nf < 4; nf++) {
                    mma_bf16(acc[mf][nf], ah[mf], bh[nf]);
                    mma_bf16(acc[mf][nf], al[mf], bh[nf]);
                    mma_bf16(acc[mf][nf], ah[mf], bl[nf]);
                }
        }
        __syncthreads();
    }
    float* Cs = (float*)(sm + KX_CS);
#pragma unroll
    for (int mf = 0; mf < 2; mf++) {
        int mA = m0 + mf*16 + r, mB = mA + 8;
#pragma unroll
        for (int nf = 0; nf < 4; nf++) {
            int c = cw + nf*8 + kq;
            Cs[mA * 132 + c    ] = acc[mf][nf][0];
            Cs[mA * 132 + c + 1] = acc[mf][nf][1];
            Cs[mB * 132 + c    ] = acc[mf][nf][2];
            Cs[mB * 132 + c + 1] = acc[mf][nf][3];
        }
    }
    __syncthreads();
#pragma unroll
    for (int i = 0; i < 8; i++) {
        int idx = t + i * 256, m = idx >> 5, g = idx & 31;
        float4 v = *(float4*)(Cs + m * 132 + 4*g);
        *(float4*)(g_KXp[ks] + ((size_t)b * M_ + m) * C_ + c0 + 4*g) = v;
    }
}

// =====================================================================
// small fp32 kernels
// =====================================================================
__global__ void rowsum_x(const float* __restrict__ x) {
    __shared__ float s[4];
    int row = blockIdx.y * 512 + blockIdx.x;
    const float* p = x + (size_t)row * N_;
    float v = 0.f;
    for (int i = threadIdx.x; i < N_ / 4; i += blockDim.x) {
        float4 q = *(const float4*)(p + 4 * i);
        v += q.x + q.y + q.z + q.w;
    }
    int lane = threadIdx.x & 31, w = threadIdx.x >> 5;
#pragma unroll
    for (int o = 16; o; o >>= 1) v += __shfl_xor_sync(0xffffffffu, v, o);
    if (lane == 0) s[w] = v;
    __syncthreads();
    if (threadIdx.x == 0) g_xsum[row] = s[0] + s[1] + s[2] + s[3];
}

__global__ void rowsum_K() {
    __shared__ float s[4];
    int row = blockIdx.y * 64 + blockIdx.x;
    const float* p = g_Kn + (size_t)row * N_;
    float v = 0.f;
    for (int i = threadIdx.x; i < N_ / 4; i += blockDim.x) {
        float4 q = *(const float4*)(p + 4 * i);
        v += q.x + q.y + q.z + q.w;
    }
    int lane = threadIdx.x & 31, w = threadIdx.x >> 5;
#pragma unroll
    for (int o = 16; o; o >>= 1) v += __shfl_xor_sync(0xffffffffu, v, o);
    if (lane == 0) s[w] = v;
    __syncthreads();
    if (threadIdx.x == 0) g_Knsum[row] = s[0] + s[1] + s[2] + s[3];
}

__global__ void tailor_kernel() {
    __shared__ float ks[64];
    int b = blockIdx.y;
    if (threadIdx.x < 64) ks[threadIdx.x] = g_Knsum[b * M_ + threadIdx.x];
    __syncthreads();
    int n = blockIdx.x * 256 + threadIdx.x;
    const float* q = g_QnT + ((size_t)b * N_ + n) * M_;
    float d = (float)N_;
#pragma unroll
    for (int g = 0; g < 16; g++) {
        float4 v = *(const float4*)(q + 4*g);
        d = fmaf(v.x, ks[4*g+0], d); d = fmaf(v.y, ks[4*g+1], d);
        d = fmaf(v.z, ks[4*g+2], d); d = fmaf(v.w, ks[4*g+3], d);
    }
    g_tailor[b * N_ + n] = 1.f / fmaxf(d, 1e-6f);
}

__global__ void sum_kx() {
    int i = blockIdx.x * 256 + threadIdx.x;   // float4 index, 131072 total
    float4 a = *(const float4*)(g_KXp[0] + 4 * (size_t)i);
    float4 c = *(const float4*)(g_KXp[1] + 4 * (size_t)i);
    float4 d = *(const float4*)(g_KXp[2] + 4 * (size_t)i);
    float4 e = *(const float4*)(g_KXp[3] + 4 * (size_t)i);
    float4 o = make_float4(a.x+c.x+d.x+e.x, a.y+c.y+d.y+e.y,
                           a.z+c.z+d.z+e.z, a.w+c.w+d.w+e.w);
    *(float4*)(g_KXs + 4 * (size_t)i) = o;
}

// mat: D[m][c] = sum_k KXs[m][k] Wv[c][k]; store matT[c][m] + bv[c]*Knsum[m]
__global__ void mat_gemm(const float* __restrict__ Wv, const float* __restrict__ bv) {
    __shared__ float As[64][65];
    __shared__ float Bs[64][65];
    int b = blockIdx.y, c0 = blockIdx.x * 64, t = threadIdx.x;
    int tm = t >> 4, tc = t & 15;
    float acc[4][4] = {};
    const float* A  = g_KXs + (size_t)b * M_ * C_;
    const float* Bm = Wv + (size_t)c0 * C_;
    for (int k0 = 0; k0 < C_; k0 += 64) {
#pragma unroll
        for (int i = 0; i < 16; i++) {
            int idx = t + i * 256, rr = idx >> 6, kk = idx & 63;
            As[rr][kk] = A [(size_t)rr * C_ + k0 + kk];
            Bs[rr][kk] = Bm[(size_t)rr * C_ + k0 + kk];
        }
        __syncthreads();
#pragma unroll
        for (int kk = 0; kk < 64; kk++) {
            float a[4], bb[4];
#pragma unroll
            for (int i = 0; i < 4; i++) a[i]  = As[tm + 16*i][kk];
#pragma unroll
            for (int j = 0; j < 4; j++) bb[j] = Bs[tc + 16*j][kk];
#pragma unroll
            for (int i = 0; i < 4; i++)
#pragma unroll
                for (int j = 0; j < 4; j++) acc[i][j] = fmaf(a[i], bb[j], acc[i][j]);
        }
        __syncthreads();
    }
#pragma unroll
    for (int i = 0; i < 4; i++) {
        int m = tm + 16*i;
        float kn = g_Knsum[b * M_ + m];
#pragma unroll
        for (int j = 0; j < 4; j++) {
            int c = c0 + tc + 16*j;
            g_matT[((size_t)b * C_ + c) * M_ + m] = acc[i][j] + bv[c] * kn;
        }
    }
}

__global__ void vsum_kernel(const float* __restrict__ Wv, const float* __restrict__ bv) {
    int b = blockIdx.y;
    int c = blockIdx.x * 4 + (threadIdx.x >> 5);
    int lane = threadIdx.x & 31;
    const float* w  = Wv + (size_t)c * C_;
    const float* xs = g_xsum + b * C_;
    float s = 0.f;
    for (int i = lane; i < C_; i += 32) s = fmaf(w[i], xs[i], s);
#pragma unroll
    for (int o = 16; o; o >>= 1) s += __shfl_xor_sync(0xffffffffu, s, o);
    if (lane == 0) g_Vsum[b * C_ + c] = s + (float)N_ * bv[c];
}

// =====================================================================
// final_mma: D[128c][128n] = matT @ QnT^T, K=64. grid (32 n, 4 c, 16 b)
// ops: Ah 0 Al 18432 Bh 36864 Bl 55296 (each 128*72*2) -> 73728
// Cs: 0 (128*132*4 = 67584); tl 73728, vs 74240; total 74752
// =====================================================================
#define FN_AH 0
#define FN_AL 18432
#define FN_BH 36864
#define FN_BL 55296
#define FN_CS 0
#define FN_TL 73728
#define FN_VS 74240
#define FN_BYTES 74752

__global__ __launch_bounds__(256, 1) void final_mma(float* __restrict__ out,
                                                    const float* __restrict__ gamma) {
    extern __shared__ __align__(16) char sm[];
    const int t = threadIdx.x, lane = t & 31, wid = t >> 5;
    const int b = blockIdx.z, c0 = blockIdx.y * 128, n0 = blockIdx.x * 128;
    float* tl = (float*)(sm + FN_TL);
    float* vs = (float*)(sm + FN_VS);
    if (t < 128) {
        tl[t] = g_tailor[(size_t)b * N_ + n0 + t];
        vs[t] = g_Vsum[b * C_ + c0 + t];
    }
    __nv_bfloat16* Ah = (__nv_bfloat16*)(sm + FN_AH);
    __nv_bfloat16* Al = (__nv_bfloat16*)(sm + FN_AL);
    __nv_bfloat16* Bh = (__nv_bfloat16*)(sm + FN_BH);
    __nv_bfloat16* Bl = (__nv_bfloat16*)(sm + FN_BL);
#pragma unroll
    for (int i = 0; i < 8; i++) {       // A: matT rows (c), 64 k
        int idx = t + i * 256, row = idx >> 4, g = idx & 15;
        float4 v = *(const float4*)(g_matT + ((size_t)b * C_ + c0 + row) * M_ + 4*g);
        uint2 h, l; split4(v, h, l);
        *(uint2*)(Ah + row * 72 + 4*g) = h;
        *(uint2*)(Al + row * 72 + 4*g) = l;
    }
#pragma unroll
    for (int i = 0; i < 8; i++) {       // B: QnT rows (n), 64 k
        int idx = t + i * 256, row = idx >> 4, g = idx & 15;
        float4 v = *(const float4*)(g_QnT + ((size_t)b * N_ + n0 + row) * M_ + 4*g);
        uint2 h, l; split4(v, h, l);
        *(uint2*)(Bh + row * 72 + 4*g) = h;
        *(uint2*)(Bl + row * 72 + 4*g) = l;
    }
    __syncthreads();

    const int cw = (wid >> 2) * 64, nw = (wid & 3) * 32;
    const int r = lane >> 2, kq = (lane & 3) * 2;
    float acc[4][4][4] = {};
#pragma unroll
    for (int kc = 0; kc < 64; kc += 16) {
        uint32_t ah[4][4], al[4][4], bh[4][2], bl[4][2];
#pragma unroll
        for (int mf = 0; mf < 4; mf++) {
            ldAf(ah[mf], (char*)Ah, 72, cw + mf*16, kc, r, kq);
            ldAf(al[mf], (char*)Al, 72, cw + mf*16, kc, r, kq);
        }
#pragma unroll
        for (int nf = 0; nf < 4; nf++) {
            ldBf(bh[nf], (char*)Bh, 72, nw + nf*8, kc, r, kq);
            ldBf(bl[nf], (char*)Bl, 72, nw + nf*8, kc, r, kq);
        }
#pragma unroll
        for (int mf = 0; mf < 4; mf++)
#pragma unroll
            for (int nf = 0; nf < 4; nf++) {
                mma_bf16(acc[mf][nf], ah[mf], bh[nf]);
                mma_bf16(acc[mf][nf], al[mf], bh[nf]);
                mma_bf16(acc[mf][nf], ah[mf], bl[nf]);
            }
    }
    __syncthreads();

    float* Cs = (float*)(sm + FN_CS);
    float gm = gamma[0];
#pragma unroll
    for (int mf = 0; mf < 4; mf++) {
        int cA = cw + mf*16 + r, cB = cA + 8;
        float vA = vs[cA], vB = vs[cB];
#pragma unroll
        for (int nf = 0; nf < 4; nf++) {
            int n = nw + nf*8 + kq;
            Cs[cA * 132 + n    ] = fixv(gm * tl[n    ] * (vA + acc[mf][nf][0]));
            Cs[cA * 132 + n + 1] = fixv(gm * tl[n + 1] * (vA + acc[mf][nf][1]));
            Cs[cB * 132 + n    ] = fixv(gm * tl[n    ] * (vB + acc[mf][nf][2]));
            Cs[cB * 132 + n + 1] = fixv(gm * tl[n + 1] * (vB + acc[mf][nf][3]));
        }
    }
    __syncthreads();
#pragma unroll
    for (int i = 0; i < 16; i++) {
        int idx = t + i * 256, c = idx >> 5, g = idx & 31;
        float4 v = *(float4*)(Cs + c * 132 + 4*g);
        *(float4*)(out + ((size_t)b * C_ + c0 + c) * N_ + n0 + 4*g) = v;
    }
}

// ---------------------------------------------------------------
extern "C" void kernel_launch(void* const* d_in, const int* in_sizes, int n_in,
                              void* d_out, int out_size) {
    const float* x     = (const float*)d_in[0];
    const float* Wq    = (const float*)d_in[1];
    const float* bq    = (const float*)d_in[2];
    const float* Wk    = (const float*)d_in[3];
    const float* bk    = (const float*)d_in[4];
    const float* Wv    = (const float*)d_in[5];
    const float* bv    = (const float*)d_in[6];
    const float* gamma = (const float*)d_in[7];
    float* out = (float*)d_out;

    cudaFuncSetAttribute(qk_mma,    cudaFuncAttributeMaxDynamicSharedMemorySize, QK_BYTES);
    cudaFuncSetAttribute(final_mma, cudaFuncAttributeMaxDynamicSharedMemorySize, FN_BYTES);

    rowsum_x     <<<dim3(512, 16), 128>>>(x);
    vsum_kernel  <<<dim3(128, 16), 128>>>(Wv, bv);
    qk_mma       <<<dim3(32, 16), 256, QK_BYTES>>>(x, Wq, bq, Wk, bk);
    rowsum_K     <<<dim3(64, 16), 128>>>();
    tailor_kernel<<<dim3(16, 16), 256>>>();
    kx_mma       <<<dim3(4, 16, 4), 256>>>(x);
    sum_kx       <<<512, 256>>>();
    mat_gemm     <<<dim3(8, 16), 256>>>(Wv, bv);
    final_mma    <<<dim3(32, 4, 16), 256, FN_BYTES>>>(out, gamma);
}

// round 5
// speedup vs baseline: 2.6066x; 1.1931x over previous
#include <cuda_runtime.h>
#include <cuda_bf16.h>
#include <cstdint>
#include <math.h>

#define B_ 16
#define C_ 512
#define N_ 4096
#define M_ 64

// ---------------- scratch (static device globals) ----------------
__device__ __align__(128) float g_QnT[B_*N_*M_];      // [b][n][m]
__device__ __align__(128) float g_Kn [B_*M_*N_];      // [b][m][n]
__device__ __align__(128) float g_KXp[4][B_*M_*C_];   // k-split partials
__device__ __align__(128) float g_KXs[B_*M_*C_];      // summed
__device__ __align__(128) float g_matT[B_*C_*M_];     // [b][c][m]
__device__ __align__(128) float g_Knsum[B_*M_];
__device__ __align__(128) float g_xsump[4][B_*C_];    // xsum k-split partials
__device__ __align__(128) float g_Vsum[B_*C_];

// ---------------- bf16 split helpers ----------------
__device__ __forceinline__ uint32_t bpk(float a, float b) {
    __nv_bfloat162 t = __floats2bfloat162_rn(a, b);
    return *reinterpret_cast<uint32_t*>(&t);
}
__device__ __forceinline__ void split4(float4 v, uint2& h, uint2& l) {
    float hx = __bfloat162float(__float2bfloat16_rn(v.x));
    float hy = __bfloat162float(__float2bfloat16_rn(v.y));
    float hz = __bfloat162float(__float2bfloat16_rn(v.z));
    float hw = __bfloat162float(__float2bfloat16_rn(v.w));
    h.x = bpk(hx, hy);             h.y = bpk(hz, hw);
    l.x = bpk(v.x - hx, v.y - hy); l.y = bpk(v.z - hz, v.w - hw);
}
__device__ __forceinline__ void split2(float a, float b, uint32_t& h, uint32_t& l) {
    float ha = __bfloat162float(__float2bfloat16_rn(a));
    float hb = __bfloat162float(__float2bfloat16_rn(b));
    h = bpk(ha, hb); l = bpk(a - ha, b - hb);
}

// ---------------- warp mma helpers ----------------
__device__ __forceinline__ void mma_bf16(float c[4], const uint32_t a[4], const uint32_t b[2]) {
    asm volatile("mma.sync.aligned.m16n8k16.row.col.f32.bf16.bf16.f32 "
        "{%0,%1,%2,%3}, {%4,%5,%6,%7}, {%8,%9}, {%0,%1,%2,%3};"
        : "+f"(c[0]), "+f"(c[1]), "+f"(c[2]), "+f"(c[3])
        : "r"(a[0]), "r"(a[1]), "r"(a[2]), "r"(a[3]), "r"(b[0]), "r"(b[1]));
}
__device__ __forceinline__ void ldAf(uint32_t a[4], const char* base, int pitch,
                                     int row, int kc, int r, int kq) {
    const __nv_bfloat16* p = (const __nv_bfloat16*)base;
    a[0] = *(const uint32_t*)(p + (row + r    ) * pitch + kc + kq);
    a[1] = *(const uint32_t*)(p + (row + r + 8) * pitch + kc + kq);
    a[2] = *(const uint32_t*)(p + (row + r    ) * pitch + kc + kq + 8);
    a[3] = *(const uint32_t*)(p + (row + r + 8) * pitch + kc + kq + 8);
}
__device__ __forceinline__ void ldBf(uint32_t bb[2], const char* base, int pitch,
                                     int row, int kc, int r, int kq) {
    const __nv_bfloat16* p = (const __nv_bfloat16*)base;
    bb[0] = *(const uint32_t*)(p + (row + r) * pitch + kc + kq);
    bb[1] = *(const uint32_t*)(p + (row + r) * pitch + kc + kq + 8);
}
__device__ __forceinline__ float fixv(float v) {
    if (isnan(v)) return 0.f;
    if (isinf(v)) return v > 0.f ? 1.f : -1.f;
    return v;
}

// =====================================================================
// qk_mma: D[128m(64q|64k)][128n] = Wqk @ x, K=512. grid(32,16), 256 thr
// Pipelined: reg-prefetch of next k-step; double-buffered panels,
// single-buffered fp32 transpose staging (safe: writes of step p+1 happen
// after sync2(p), which follows all transpose reads of step p).
// smem (bytes): Ah 0/10240, Al 20480/30720, Bh 40960/51200, Bl 61440/71680,
//               Ss 81920 (16896), bias 98816, inq 99328, ink 99840 -> 100352
// epilogue Cs at 0 (128*133*4 = 68096)
// =====================================================================
#define QK_A(h, s)  ((h) * 20480 + (s) * 10240)
#define QK_B(h, s)  (40960 + (h) * 20480 + (s) * 10240)
#define QK_SS 81920
#define QK_CS 0
#define QK_BIAS 98816
#define QK_INQ 99328
#define QK_INK 99840
#define QK_BYTES 100352

__global__ __launch_bounds__(256, 1) void qk_mma(
    const float* __restrict__ x,  const float* __restrict__ Wq,
    const float* __restrict__ bq, const float* __restrict__ Wk,
    const float* __restrict__ bk) {
    extern __shared__ __align__(16) char sm[];
    const int t = threadIdx.x, lane = t & 31, wid = t >> 5;
    const int b = blockIdx.y, n0 = blockIdx.x * 128;
    const float* xb = x + (size_t)b * C_ * N_;
    float* bias = (float*)(sm + QK_BIAS);
    float* inq  = (float*)(sm + QK_INQ);
    float* ink  = (float*)(sm + QK_INK);
    if (t < 128) bias[t] = (t < 64) ? bq[t] : bk[t - 64];

    const int m0 = (wid >> 2) * 64, nw = (wid & 3) * 32;
    const int r = lane >> 2, kq = (lane & 3) * 2;
    float acc[4][4][4] = {};
    float* Ss = (float*)(sm + QK_SS);

    float4 aR[4], xR[4];
    // prologue: load k-step 0 into registers
#pragma unroll
    for (int i = 0; i < 4; i++) {
        int idx = t + i * 256, row = idx >> 3, g = idx & 7;
        aR[i] = (row < 64) ? *(const float4*)(Wq + (size_t)row * C_ + 4*g)
                           : *(const float4*)(Wk + (size_t)(row - 64) * C_ + 4*g);
    }
#pragma unroll
    for (int i = 0; i < 4; i++) {
        int idx = t + i * 256, kk = idx >> 5, g = idx & 31;
        xR[i] = *(const float4*)(xb + (size_t)kk * N_ + n0 + 4*g);
    }

    for (int p = 0; p < 16; ++p) {
        const int s = p & 1;
        __nv_bfloat16* Ah = (__nv_bfloat16*)(sm + QK_A(0, s));
        __nv_bfloat16* Al = (__nv_bfloat16*)(sm + QK_A(1, s));
        __nv_bfloat16* Bh = (__nv_bfloat16*)(sm + QK_B(0, s));
        __nv_bfloat16* Bl = (__nv_bfloat16*)(sm + QK_B(1, s));
        // store A (split) + x staging from registers
#pragma unroll
        for (int i = 0; i < 4; i++) {
            int idx = t + i * 256, row = idx >> 3, g = idx & 7;
            uint2 h, l; split4(aR[i], h, l);
            *(uint2*)(Ah + row * 40 + 4*g) = h;
            *(uint2*)(Al + row * 40 + 4*g) = l;
        }
#pragma unroll
        for (int i = 0; i < 4; i++) {
            int idx = t + i * 256, kk = idx >> 5, g = idx & 31;
            *(float4*)(Ss + kk * 132 + 4*g) = xR[i];
        }
        __syncthreads();
        // prefetch next k-step (latency hidden behind transpose + mma)
        if (p < 15) {
            const int k0 = (p + 1) * 32;
#pragma unroll
            for (int i = 0; i < 4; i++) {
                int idx = t + i * 256, row = idx >> 3, g = idx & 7;
                aR[i] = (row < 64) ? *(const float4*)(Wq + (size_t)row * C_ + k0 + 4*g)
                                   : *(const float4*)(Wk + (size_t)(row - 64) * C_ + k0 + 4*g);
            }
#pragma unroll
            for (int i = 0; i < 4; i++) {
                int idx = t + i * 256, kk = idx >> 5, g = idx & 31;
                xR[i] = *(const float4*)(xb + (size_t)(k0 + kk) * N_ + n0 + 4*g);
            }
        }
        // transpose staging -> B panels (split)
        {
            int n = t & 127, kh = (t >> 7) * 16;
#pragma unroll
            for (int j = 0; j < 16; j += 2) {
                float v0 = Ss[(kh + j) * 132 + n], v1 = Ss[(kh + j + 1) * 132 + n];
                uint32_t h, l; split2(v0, v1, h, l);
                *(uint32_t*)(Bh + n * 40 + kh + j) = h;
                *(uint32_t*)(Bl + n * 40 + kh + j) = l;
            }
        }
        __syncthreads();
        // mma on current panels
#pragma unroll
        for (int kc = 0; kc < 32; kc += 16) {
            uint32_t ah[4][4], al[4][4], bh[4][2], bl[4][2];
#pragma unroll
            for (int mf = 0; mf < 4; mf++) {
                ldAf(ah[mf], (char*)Ah, 40, m0 + mf*16, kc, r, kq);
                ldAf(al[mf], (char*)Al, 40, m0 + mf*16, kc, r, kq);
            }
#pragma unroll
            for (int nf = 0; nf < 4; nf++) {
                ldBf(bh[nf], (char*)Bh, 40, nw + nf*8, kc, r, kq);
                ldBf(bl[nf], (char*)Bl, 40, nw + nf*8, kc, r, kq);
            }
#pragma unroll
            for (int mf = 0; mf < 4; mf++)
#pragma unroll
                for (int nf = 0; nf < 4; nf++) {
                    mma_bf16(acc[mf][nf], ah[mf], bh[nf]);
                    mma_bf16(acc[mf][nf], al[mf], bh[nf]);
                    mma_bf16(acc[mf][nf], ah[mf], bl[nf]);
                }
        }
    }
    __syncthreads();   // panels no longer needed; reuse smem as Cs

    // ---- epilogue: stage to Cs (fp32, pitch 133) with bias ----
    float* Cs = (float*)(sm + QK_CS);
#pragma unroll
    for (int mf = 0; mf < 4; mf++) {
        int mA = m0 + mf*16 + r, mB = mA + 8;
        float bA = bias[mA], bB = bias[mB];
#pragma unroll
        for (int nf = 0; nf < 4; nf++) {
            int n = nw + nf*8 + kq;
            Cs[mA * 133 + n    ] = acc[mf][nf][0] + bA;
            Cs[mA * 133 + n + 1] = acc[mf][nf][1] + bA;
            Cs[mB * 133 + n    ] = acc[mf][nf][2] + bB;
            Cs[mB * 133 + n + 1] = acc[mf][nf][3] + bB;
        }
    }
    __syncthreads();
    // ---- per-column L2 norms ----
    {
        int n = t & 127, part = t >> 7, base = part * 64;
        float s = 0.f;
#pragma unroll 8
        for (int m = 0; m < 64; m++) {
            float v = Cs[(base + m) * 133 + n]; s = fmaf(v, v, s);
        }
        float inv = 1.f / fmaxf(sqrtf(s), 1e-6f);
        if (part == 0) inq[n] = inv; else ink[n] = inv;
    }
    __syncthreads();
    // ---- write Kn[m][n] (coalesced) ----
#pragma unroll
    for (int i = 0; i < 8; i++) {
        int idx = t + i * 256, m = idx >> 5, g = idx & 31;
        float4 v;
        v.x = Cs[(64 + m) * 133 + 4*g + 0] * ink[4*g + 0];
        v.y = Cs[(64 + m) * 133 + 4*g + 1] * ink[4*g + 1];
        v.z = Cs[(64 + m) * 133 + 4*g + 2] * ink[4*g + 2];
        v.w = Cs[(64 + m) * 133 + 4*g + 3] * ink[4*g + 3];
        *(float4*)(g_Kn + ((size_t)b * M_ + m) * N_ + n0 + 4*g) = v;
    }
    // ---- write QnT[n][m] ----
#pragma unroll
    for (int i = 0; i < 8; i++) {
        int idx = t + i * 256, n = idx >> 4, g = idx & 15;
        float iq = inq[n];
        float4 v;
        v.x = Cs[(4*g + 0) * 133 + n] * iq;
        v.y = Cs[(4*g + 1) * 133 + n] * iq;
        v.z = Cs[(4*g + 2) * 133 + n] * iq;
        v.w = Cs[(4*g + 3) * 133 + n] * iq;
        *(float4*)(g_QnT + ((size_t)b * N_ + n0 + n) * M_ + 4*g) = v;
    }
}

// =====================================================================
// kx_mma: D[64m][128c] = Kn @ x^T over k-slice of 1024 (pipelined, 1 sync/iter).
// Also accumulates per-ksplit xsum partials (deterministic, no atomics).
// grid (4 c-tiles, 16 b, 4 ksplit), 256 thr, dynamic smem.
// smem: Ah 0/5120, Al 10240/15360, Bh 20480/30720, Bl 40960/51200 -> 61440
// epilogue Cs at 0 (64*132*4 = 33792)
// =====================================================================
#define KX_A(h, s) ((h) * 10240 + (s) * 5120)
#define KX_B(h, s) (20480 + (h) * 20480 + (s) * 10240)
#define KX_CS 0
#define KX_BYTES 61440

__global__ __launch_bounds__(256, 1) void kx_mma(const float* __restrict__ x) {
    extern __shared__ __align__(16) char sm[];
    const int t = threadIdx.x, lane = t & 31, wid = t >> 5;
    const int b = blockIdx.y, c0 = blockIdx.x * 128, ks = blockIdx.z;
    const float* Kb = g_Kn + (size_t)b * M_ * N_;
    const float* xb = x + (size_t)b * C_ * N_ + (size_t)c0 * N_;
    const int m0 = (wid >> 2) * 32, cw = (wid & 3) * 32;
    const int r = lane >> 2, kq = (lane & 3) * 2;
    float acc[2][4][4] = {};
    float xs[4] = {0.f, 0.f, 0.f, 0.f};

    float4 aR[2], bR[4];
    // prologue: load + store step 0
    {
        const int k0 = ks * 1024;
#pragma unroll
        for (int i = 0; i < 2; i++) {
            int idx = t + i * 256, row = idx >> 3, g = idx & 7;
            aR[i] = *(const float4*)(Kb + (size_t)row * N_ + k0 + 4*g);
        }
#pragma unroll
        for (int i = 0; i < 4; i++) {
            int idx = t + i * 256, row = idx >> 3, g = idx & 7;
            bR[i] = *(const float4*)(xb + (size_t)row * N_ + k0 + 4*g);
        }
        __nv_bfloat16* Ah = (__nv_bfloat16*)(sm + KX_A(0, 0));
        __nv_bfloat16* Al = (__nv_bfloat16*)(sm + KX_A(1, 0));
        __nv_bfloat16* Bh = (__nv_bfloat16*)(sm + KX_B(0, 0));
        __nv_bfloat16* Bl = (__nv_bfloat16*)(sm + KX_B(1, 0));
#pragma unroll
        for (int i = 0; i < 2; i++) {
            int idx = t + i * 256, row = idx >> 3, g = idx & 7;
            uint2 h, l; split4(aR[i], h, l);
            *(uint2*)(Ah + row * 40 + 4*g) = h;
            *(uint2*)(Al + row * 40 + 4*g) = l;
        }
#pragma unroll
        for (int i = 0; i < 4; i++) {
            int idx = t + i * 256, row = idx >> 3, g = idx & 7;
            xs[i] += bR[i].x + bR[i].y + bR[i].z + bR[i].w;
            uint2 h, l; split4(bR[i], h, l);
            *(uint2*)(Bh + row * 40 + 4*g) = h;
            *(uint2*)(Bl + row * 40 + 4*g) = l;
        }
    }
    __syncthreads();

    for (int p = 0; p < 32; ++p) {
        const int s = p & 1;
        if (p < 31) {   // prefetch next step
            const int k0 = ks * 1024 + (p + 1) * 32;
#pragma unroll
            for (int i = 0; i < 2; i++) {
                int idx = t + i * 256, row = idx >> 3, g = idx & 7;
                aR[i] = *(const float4*)(Kb + (size_t)row * N_ + k0 + 4*g);
            }
#pragma unroll
            for (int i = 0; i < 4; i++) {
                int idx = t + i * 256, row = idx >> 3, g = idx & 7;
                bR[i] = *(const float4*)(xb + (size_t)row * N_ + k0 + 4*g);
            }
        }
        // mma on current stage
        {
            __nv_bfloat16* Ah = (__nv_bfloat16*)(sm + KX_A(0, s));
            __nv_bfloat16* Al = (__nv_bfloat16*)(sm + KX_A(1, s));
            __nv_bfloat16* Bh = (__nv_bfloat16*)(sm + KX_B(0, s));
            __nv_bfloat16* Bl = (__nv_bfloat16*)(sm + KX_B(1, s));
#pragma unroll
            for (int kc = 0; kc < 32; kc += 16) {
                uint32_t ah[2][4], al[2][4], bh[4][2], bl[4][2];
#pragma unroll
                for (int mf = 0; mf < 2; mf++) {
                    ldAf(ah[mf], (char*)Ah, 40, m0 + mf*16, kc, r, kq);
                    ldAf(al[mf], (char*)Al, 40, m0 + mf*16, kc, r, kq);
                }
#pragma unroll
                for (int nf = 0; nf < 4; nf++) {
                    ldBf(bh[nf], (char*)Bh, 40, cw + nf*8, kc, r, kq);
                    ldBf(bl[nf], (char*)Bl, 40, cw + nf*8, kc, r, kq);
                }
#pragma unroll
                for (int mf = 0; mf < 2; mf++)
#pragma unroll
                    for (int nf = 0; nf < 4; nf++) {
                        mma_bf16(acc[mf][nf], ah[mf], bh[nf]);
                        mma_bf16(acc[mf][nf], al[mf], bh[nf]);
                        mma_bf16(acc[mf][nf], ah[mf], bl[nf]);
                    }
            }
        }
        // store next stage
        if (p < 31) {
            const int sn = (p + 1) & 1;
            __nv_bfloat16* Ah = (__nv_bfloat16*)(sm + KX_A(0, sn));
            __nv_bfloat16* Al = (__nv_bfloat16*)(sm + KX_A(1, sn));
            __nv_bfloat16* Bh = (__nv_bfloat16*)(sm + KX_B(0, sn));
            __nv_bfloat16* Bl = (__nv_bfloat16*)(sm + KX_B(1, sn));
#pragma unroll
            for (int i = 0; i < 2; i++) {
                int idx = t + i * 256, row = idx >> 3, g = idx & 7;
                uint2 h, l; split4(aR[i], h, l);
                *(uint2*)(Ah + row * 40 + 4*g) = h;
                *(uint2*)(Al + row * 40 + 4*g) = l;
            }
#pragma unroll
            for (int i = 0; i < 4; i++) {
                int idx = t + i * 256, row = idx >> 3, g = idx & 7;
                xs[i] += bR[i].x + bR[i].y + bR[i].z + bR[i].w;
                uint2 h, l; split4(bR[i], h, l);
                *(uint2*)(Bh + row * 40 + 4*g) = h;
                *(uint2*)(Bl + row * 40 + 4*g) = l;
            }
        }
        __syncthreads();
    }

    // xsum partial: reduce over the 8 column-group threads per row, store
#pragma unroll
    for (int i = 0; i < 4; i++) {
        float v = xs[i];
        v += __shfl_xor_sync(0xffffffffu, v, 1);
        v += __shfl_xor_sync(0xffffffffu, v, 2);
        v += __shfl_xor_sync(0xffffffffu, v, 4);
        if ((t & 7) == 0)
            g_xsump[ks][b * C_ + c0 + (t >> 3) + 32 * i] = v;
    }

    // epilogue via smem staging (panels dead; reuse)
    float* Cs = (float*)(sm + KX_CS);
#pragma unroll
    for (int mf = 0; mf < 2; mf++) {
        int mA = m0 + mf*16 + r, mB = mA + 8;
#pragma unroll
        for (int nf = 0; nf < 4; nf++) {
            int c = cw + nf*8 + kq;
            Cs[mA * 132 + c    ] = acc[mf][nf][0];
            Cs[mA * 132 + c + 1] = acc[mf][nf][1];
            Cs[mB * 132 + c    ] = acc[mf][nf][2];
            Cs[mB * 132 + c + 1] = acc[mf][nf][3];
        }
    }
    __syncthreads();
#pragma unroll
    for (int i = 0; i < 8; i++) {
        int idx = t + i * 256, m = idx >> 5, g = idx & 31;
        float4 v = *(float4*)(Cs + m * 132 + 4*g);
        *(float4*)(g_KXp[ks] + ((size_t)b * M_ + m) * C_ + c0 + 4*g) = v;
    }
}

// =====================================================================
// small fp32 kernels
// =====================================================================
__global__ void rowsum_K() {
    __shared__ float s[4];
    int row = blockIdx.y * 64 + blockIdx.x;
    const float* p = g_Kn + (size_t)row * N_;
    float v = 0.f;
    for (int i = threadIdx.x; i < N_ / 4; i += blockDim.x) {
        float4 q = *(const float4*)(p + 4 * i);
        v += q.x + q.y + q.z + q.w;
    }
    int lane = threadIdx.x & 31, w = threadIdx.x >> 5;
#pragma unroll
    for (int o = 16; o; o >>= 1) v += __shfl_xor_sync(0xffffffffu, v, o);
    if (lane == 0) s[w] = v;
    __syncthreads();
    if (threadIdx.x == 0) g_Knsum[row] = s[0] + s[1] + s[2] + s[3];
}

__global__ void sum_kx() {
    int i = blockIdx.x * 256 + threadIdx.x;   // float4 index
    float4 a = *(const float4*)(g_KXp[0] + 4 * (size_t)i);
    float4 c = *(const float4*)(g_KXp[1] + 4 * (size_t)i);
    float4 d = *(const float4*)(g_KXp[2] + 4 * (size_t)i);
    float4 e = *(const float4*)(g_KXp[3] + 4 * (size_t)i);
    float4 o = make_float4(a.x+c.x+d.x+e.x, a.y+c.y+d.y+e.y,
                           a.z+c.z+d.z+e.z, a.w+c.w+d.w+e.w);
    *(float4*)(g_KXs + 4 * (size_t)i) = o;
}

__global__ void vsum_kernel(const float* __restrict__ Wv, const float* __restrict__ bv) {
    int b = blockIdx.y;
    int c = blockIdx.x * 4 + (threadIdx.x >> 5);
    int lane = threadIdx.x & 31;
    const float* w = Wv + (size_t)c * C_;
    float s = 0.f;
    for (int i = lane; i < C_; i += 32) {
        float xsv = g_xsump[0][b * C_ + i] + g_xsump[1][b * C_ + i]
                  + g_xsump[2][b * C_ + i] + g_xsump[3][b * C_ + i];
        s = fmaf(w[i], xsv, s);
    }
#pragma unroll
    for (int o = 16; o; o >>= 1) s += __shfl_xor_sync(0xffffffffu, s, o);
    if (lane == 0) g_Vsum[b * C_ + c] = s + (float)N_ * bv[c];
}

// mat: D[m][c] = sum_k KXs[m][k] Wv[c][k]; store matT[c][m] + bv[c]*Knsum[m]
__global__ void mat_gemm(const float* __restrict__ Wv, const float* __restrict__ bv) {
    __shared__ float As[64][65];
    __shared__ float Bs[64][65];
    int b = blockIdx.y, c0 = blockIdx.x * 64, t = threadIdx.x;
    int tm = t >> 4, tc = t & 15;
    float acc[4][4] = {};
    const float* A  = g_KXs + (size_t)b * M_ * C_;
    const float* Bm = Wv + (size_t)c0 * C_;
    for (int k0 = 0; k0 < C_; k0 += 64) {
#pragma unroll
        for (int i = 0; i < 16; i++) {
            int idx = t + i * 256, rr = idx >> 6, kk = idx & 63;
            As[rr][kk] = A [(size_t)rr * C_ + k0 + kk];
            Bs[rr][kk] = Bm[(size_t)rr * C_ + k0 + kk];
        }
        __syncthreads();
#pragma unroll
        for (int kk = 0; kk < 64; kk++) {
            float a[4], bb[4];
#pragma unroll
            for (int i = 0; i < 4; i++) a[i]  = As[tm + 16*i][kk];
#pragma unroll
            for (int j = 0; j < 4; j++) bb[j] = Bs[tc + 16*j][kk];
#pragma unroll
            for (int i = 0; i < 4; i++)
#pragma unroll
                for (int j = 0; j < 4; j++) acc[i][j] = fmaf(a[i], bb[j], acc[i][j]);
        }
        __syncthreads();
    }
#pragma unroll
    for (int i = 0; i < 4; i++) {
        int m = tm + 16*i;
        float kn = g_Knsum[b * M_ + m];
#pragma unroll
        for (int j = 0; j < 4; j++) {
            int c = c0 + tc + 16*j;
            g_matT[((size_t)b * C_ + c) * M_ + m] = acc[i][j] + bv[c] * kn;
        }
    }
}

// =====================================================================
// final_mma: D[128c][128n] = matT @ QnT^T, K=64, with fused tailor compute.
// grid (32 n, 4 c, 16 b), 256 thr.
// smem: Ah 0 Al 18432 Bh 36864 Bl 55296 -> 73728; tl 73728, vs 74240,
//       ks 74752 -> 75008. Epilogue Cs at 0 (67584).
// =====================================================================
#define FN_AH 0
#define FN_AL 18432
#define FN_BH 36864
#define FN_BL 55296
#define FN_CS 0
#define FN_TL 73728
#define FN_VS 74240
#define FN_KS 74752
#define FN_BYTES 75008

__global__ __launch_bounds__(256, 1) void final_mma(float* __restrict__ out,
                                                    const float* __restrict__ gamma) {
    extern __shared__ __align__(16) char sm[];
    const int t = threadIdx.x, lane = t & 31, wid = t >> 5;
    const int b = blockIdx.z, c0 = blockIdx.y * 128, n0 = blockIdx.x * 128;
    float* tl = (float*)(sm + FN_TL);
    float* vs = (float*)(sm + FN_VS);
    float* ks = (float*)(sm + FN_KS);
    if (t < 128) vs[t] = g_Vsum[b * C_ + c0 + t];
    if (t < 64)  ks[t] = g_Knsum[b * M_ + t];
    __nv_bfloat16* Ah = (__nv_bfloat16*)(sm + FN_AH);
    __nv_bfloat16* Al = (__nv_bfloat16*)(sm + FN_AL);
    __nv_bfloat16* Bh = (__nv_bfloat16*)(sm + FN_BH);
    __nv_bfloat16* Bl = (__nv_bfloat16*)(sm + FN_BL);
#pragma unroll
    for (int i = 0; i < 8; i++) {       // A: matT rows (c), 64 k
        int idx = t + i * 256, row = idx >> 4, g = idx & 15;
        float4 v = *(const float4*)(g_matT + ((size_t)b * C_ + c0 + row) * M_ + 4*g);
        uint2 h, l; split4(v, h, l);
        *(uint2*)(Ah + row * 72 + 4*g) = h;
        *(uint2*)(Al + row * 72 + 4*g) = l;
    }
#pragma unroll
    for (int i = 0; i < 8; i++) {       // B: QnT rows (n), 64 k
        int idx = t + i * 256, row = idx >> 4, g = idx & 15;
        float4 v = *(const float4*)(g_QnT + ((size_t)b * N_ + n0 + row) * M_ + 4*g);
        uint2 h, l; split4(v, h, l);
        *(uint2*)(Bh + row * 72 + 4*g) = h;
        *(uint2*)(Bl + row * 72 + 4*g) = l;
    }
    __syncthreads();

    // fused tailor: tl[n] = 1/max(N + Qn[n,:].Knsum, 1e-6)
    if (t < 128) {
        float d = (float)N_;
#pragma unroll
        for (int m = 0; m < 64; m++)
            d += (__bfloat162float(Bh[t * 72 + m]) + __bfloat162float(Bl[t * 72 + m])) * ks[m];
        tl[t] = 1.f / fmaxf(d, 1e-6f);
    }

    const int cw = (wid >> 2) * 64, nw = (wid & 3) * 32;
    const int r = lane >> 2, kq = (lane & 3) * 2;
    float acc[4][4][4] = {};
#pragma unroll
    for (int kc = 0; kc < 64; kc += 16) {
        uint32_t ah[4][4], al[4][4], bh[4][2], bl[4][2];
#pragma unroll
        for (int mf = 0; mf < 4; mf++) {
            ldAf(ah[mf], (char*)Ah, 72, cw + mf*16, kc, r, kq);
            ldAf(al[mf], (char*)Al, 72, cw + mf*16, kc, r, kq);
        }
#pragma unroll
        for (int nf = 0; nf < 4; nf++) {
            ldBf(bh[nf], (char*)Bh, 72, nw + nf*8, kc, r, kq);
            ldBf(bl[nf], (char*)Bl, 72, nw + nf*8, kc, r, kq);
        }
#pragma unroll
        for (int mf = 0; mf < 4; mf++)
#pragma unroll
            for (int nf = 0; nf < 4; nf++) {
                mma_bf16(acc[mf][nf], ah[mf], bh[nf]);
                mma_bf16(acc[mf][nf], al[mf], bh[nf]);
                mma_bf16(acc[mf][nf], ah[mf], bl[nf]);
            }
    }
    __syncthreads();

    float* Cs = (float*)(sm + FN_CS);
    float gm = gamma[0];
#pragma unroll
    for (int mf = 0; mf < 4; mf++) {
        int cA = cw + mf*16 + r, cB = cA + 8;
        float vA = vs[cA], vB = vs[cB];
#pragma unroll
        for (int nf = 0; nf < 4; nf++) {
            int n = nw + nf*8 + kq;
            Cs[cA * 132 + n    ] = fixv(gm * tl[n    ] * (vA + acc[mf][nf][0]));
            Cs[cA * 132 + n + 1] = fixv(gm * tl[n + 1] * (vA + acc[mf][nf][1]));
            Cs[cB * 132 + n    ] = fixv(gm * tl[n    ] * (vB + acc[mf][nf][2]));
            Cs[cB * 132 + n + 1] = fixv(gm * tl[n + 1] * (vB + acc[mf][nf][3]));
        }
    }
    __syncthreads();
#pragma unroll
    for (int i = 0; i < 16; i++) {
        int idx = t + i * 256, c = idx >> 5, g = idx & 31;
        float4 v = *(float4*)(Cs + c * 132 + 4*g);
        *(float4*)(out + ((size_t)b * C_ + c0 + c) * N_ + n0 + 4*g) = v;
    }
}

// ---------------------------------------------------------------
extern "C" void kernel_launch(void* const* d_in, const int* in_sizes, int n_in,
                              void* d_out, int out_size) {
    const float* x     = (const float*)d_in[0];
    const float* Wq    = (const float*)d_in[1];
    const float* bq    = (const float*)d_in[2];
    const float* Wk    = (const float*)d_in[3];
    const float* bk    = (const float*)d_in[4];
    const float* Wv    = (const float*)d_in[5];
    const float* bv    = (const float*)d_in[6];
    const float* gamma = (const float*)d_in[7];
    float* out = (float*)d_out;

    cudaFuncSetAttribute(qk_mma,    cudaFuncAttributeMaxDynamicSharedMemorySize, QK_BYTES);
    cudaFuncSetAttribute(kx_mma,    cudaFuncAttributeMaxDynamicSharedMemorySize, KX_BYTES);
    cudaFuncSetAttribute(final_mma, cudaFuncAttributeMaxDynamicSharedMemorySize, FN_BYTES);

    qk_mma       <<<dim3(32, 16), 256, QK_BYTES>>>(x, Wq, bq, Wk, bk);
    rowsum_K     <<<dim3(64, 16), 128>>>();
    kx_mma       <<<dim3(4, 16, 4), 256, KX_BYTES>>>(x);
    sum_kx       <<<512, 256>>>();
    vsum_kernel  <<<dim3(128, 16), 128>>>(Wv, bv);
    mat_gemm     <<<dim3(8, 16), 256>>>(Wv, bv);
    final_mma    <<<dim3(32, 4, 16), 256, FN_BYTES>>>(out, gamma);
}

// round 6
// speedup vs baseline: 3.1017x; 1.1900x over previous
#include <cuda_runtime.h>
#include <cuda_fp16.h>
#include <cstdint>
#include <math.h>

#define B_ 16
#define C_ 512
#define N_ 4096
#define M_ 64

// ---------------- scratch (static device globals) ----------------
__device__ __align__(128) float g_QnT[B_*N_*M_];      // [b][n][m]
__device__ __align__(128) float g_Kn [B_*M_*N_];      // [b][m][n]
__device__ __align__(128) float g_KXp[4][B_*M_*C_];   // k-split partials
__device__ __align__(128) float g_matT[B_*C_*M_];     // [b][c][m]
__device__ __align__(128) float g_Knp[B_*32*M_];      // Knsum partials per n-tile
__device__ __align__(128) float g_Knsum[B_*M_];
__device__ __align__(128) float g_xsump[4][B_*C_];    // xsum k-split partials
__device__ __align__(128) float g_Vsum[B_*C_];

// ---------------- fp16 pack helpers ----------------
__device__ __forceinline__ uint32_t hpk2(float a, float b) {
    __half2 t = __floats2half2_rn(a, b);
    return *reinterpret_cast<uint32_t*>(&t);
}
__device__ __forceinline__ uint2 pk4(float4 v) {
    uint2 r; r.x = hpk2(v.x, v.y); r.y = hpk2(v.z, v.w); return r;
}

// ---------------- warp mma helpers ----------------
__device__ __forceinline__ void mma_f16(float c[4], const uint32_t a[4], const uint32_t b[2]) {
    asm volatile("mma.sync.aligned.m16n8k16.row.col.f32.f16.f16.f32 "
        "{%0,%1,%2,%3}, {%4,%5,%6,%7}, {%8,%9}, {%0,%1,%2,%3};"
        : "+f"(c[0]), "+f"(c[1]), "+f"(c[2]), "+f"(c[3])
        : "r"(a[0]), "r"(a[1]), "r"(a[2]), "r"(a[3]), "r"(b[0]), "r"(b[1]));
}
__device__ __forceinline__ void ldAf(uint32_t a[4], const char* base, int pitch,
                                     int row, int kc, int r, int kq) {
    const __half* p = (const __half*)base;
    a[0] = *(const uint32_t*)(p + (row + r    ) * pitch + kc + kq);
    a[1] = *(const uint32_t*)(p + (row + r + 8) * pitch + kc + kq);
    a[2] = *(const uint32_t*)(p + (row + r    ) * pitch + kc + kq + 8);
    a[3] = *(const uint32_t*)(p + (row + r + 8) * pitch + kc + kq + 8);
}
__device__ __forceinline__ void ldBf(uint32_t bb[2], const char* base, int pitch,
                                     int row, int kc, int r, int kq) {
    const __half* p = (const __half*)base;
    bb[0] = *(const uint32_t*)(p + (row + r) * pitch + kc + kq);
    bb[1] = *(const uint32_t*)(p + (row + r) * pitch + kc + kq + 8);
}
__device__ __forceinline__ float fixv(float v) {
    if (isnan(v)) return 0.f;
    if (isinf(v)) return v > 0.f ? 1.f : -1.f;
    return v;
}

// =====================================================================
// qk_mma: D[128m(64q|64k)][128n] = Wqk @ x, K=512. grid(32,16), 256 thr
// fp16 single-pass, reg-prefetch pipeline, double-buffered panels.
// smem: A 0/10240 (2 stages), B 20480/30720, Ss 40960 (16896) -> 57856
// epilogue Cs at 0 (128*133*4=68096); bias 68096, inq 68608, ink 69120
// =====================================================================
#define QK_A(s)  ((s) * 10240)
#define QK_B(s)  (20480 + (s) * 10240)
#define QK_SS 40960
#define QK_CS 0
#define QK_BIAS 68096
#define QK_INQ 68608
#define QK_INK 69120
#define QK_BYTES 69632

__global__ __launch_bounds__(256, 1) void qk_mma(
    const float* __restrict__ x,  const float* __restrict__ Wq,
    const float* __restrict__ bq, const float* __restrict__ Wk,
    const float* __restrict__ bk) {
    extern __shared__ __align__(16) char sm[];
    const int t = threadIdx.x, lane = t & 31, wid = t >> 5;
    const int b = blockIdx.y, n0 = blockIdx.x * 128;
    const float* xb = x + (size_t)b * C_ * N_;
    float* bias = (float*)(sm + QK_BIAS);
    float* inq  = (float*)(sm + QK_INQ);
    float* ink  = (float*)(sm + QK_INK);
    if (t < 128) bias[t] = (t < 64) ? bq[t] : bk[t - 64];

    const int m0 = (wid >> 2) * 64, nw = (wid & 3) * 32;
    const int r = lane >> 2, kq = (lane & 3) * 2;
    float acc[4][4][4] = {};
    float* Ss = (float*)(sm + QK_SS);

    float4 aR[4], xR[4];
#pragma unroll
    for (int i = 0; i < 4; i++) {
        int idx = t + i * 256, row = idx >> 3, g = idx & 7;
        aR[i] = (row < 64) ? *(const float4*)(Wq + (size_t)row * C_ + 4*g)
                           : *(const float4*)(Wk + (size_t)(row - 64) * C_ + 4*g);
    }
#pragma unroll
    for (int i = 0; i < 4; i++) {
        int idx = t + i * 256, kk = idx >> 5, g = idx & 31;
        xR[i] = *(const float4*)(xb + (size_t)kk * N_ + n0 + 4*g);
    }

    for (int p = 0; p < 16; ++p) {
        const int s = p & 1;
        __half* Ah = (__half*)(sm + QK_A(s));
        __half* Bh = (__half*)(sm + QK_B(s));
#pragma unroll
        for (int i = 0; i < 4; i++) {
            int idx = t + i * 256, row = idx >> 3, g = idx & 7;
            *(uint2*)(Ah + row * 40 + 4*g) = pk4(aR[i]);
        }
#pragma unroll
        for (int i = 0; i < 4; i++) {
            int idx = t + i * 256, kk = idx >> 5, g = idx & 31;
            *(float4*)(Ss + kk * 132 + 4*g) = xR[i];
        }
        __syncthreads();
        if (p < 15) {   // prefetch next step
            const int k0 = (p + 1) * 32;
#pragma unroll
            for (int i = 0; i < 4; i++) {
                int idx = t + i * 256, row = idx >> 3, g = idx & 7;
                aR[i] = (row < 64) ? *(const float4*)(Wq + (size_t)row * C_ + k0 + 4*g)
                                   : *(const float4*)(Wk + (size_t)(row - 64) * C_ + k0 + 4*g);
            }
#pragma unroll
            for (int i = 0; i < 4; i++) {
                int idx = t + i * 256, kk = idx >> 5, g = idx & 31;
                xR[i] = *(const float4*)(xb + (size_t)(k0 + kk) * N_ + n0 + 4*g);
            }
        }
        // transpose staging -> B panel (fp16)
        {
            int n = t & 127, kh = (t >> 7) * 16;
#pragma unroll
            for (int j = 0; j < 16; j += 2) {
                float v0 = Ss[(kh + j) * 132 + n], v1 = Ss[(kh + j + 1) * 132 + n];
                *(uint32_t*)(Bh + n * 40 + kh + j) = hpk2(v0, v1);
            }
        }
        __syncthreads();
#pragma unroll
        for (int kc = 0; kc < 32; kc += 16) {
            uint32_t ah[4][4], bh[4][2];
#pragma unroll
            for (int mf = 0; mf < 4; mf++) ldAf(ah[mf], (char*)Ah, 40, m0 + mf*16, kc, r, kq);
#pragma unroll
            for (int nf = 0; nf < 4; nf++) ldBf(bh[nf], (char*)Bh, 40, nw + nf*8, kc, r, kq);
#pragma unroll
            for (int mf = 0; mf < 4; mf++)
#pragma unroll
                for (int nf = 0; nf < 4; nf++) mma_f16(acc[mf][nf], ah[mf], bh[nf]);
        }
    }
    __syncthreads();   // panels dead; reuse smem as Cs

    float* Cs = (float*)(sm + QK_CS);
#pragma unroll
    for (int mf = 0; mf < 4; mf++) {
        int mA = m0 + mf*16 + r, mB = mA + 8;
        float bA = bias[mA], bB = bias[mB];
#pragma unroll
        for (int nf = 0; nf < 4; nf++) {
            int n = nw + nf*8 + kq;
            Cs[mA * 133 + n    ] = acc[mf][nf][0] + bA;
            Cs[mA * 133 + n + 1] = acc[mf][nf][1] + bA;
            Cs[mB * 133 + n    ] = acc[mf][nf][2] + bB;
            Cs[mB * 133 + n + 1] = acc[mf][nf][3] + bB;
        }
    }
    __syncthreads();
    {   // per-column L2 norms
        int n = t & 127, part = t >> 7, base = part * 64;
        float s = 0.f;
#pragma unroll 8
        for (int m = 0; m < 64; m++) {
            float v = Cs[(base + m) * 133 + n]; s = fmaf(v, v, s);
        }
        float inv = 1.f / fmaxf(sqrtf(s), 1e-6f);
        if (part == 0) inq[n] = inv; else ink[n] = inv;
    }
    __syncthreads();
    // write Kn[m][n] + Knsum partials (warp-uniform m per iteration)
#pragma unroll
    for (int i = 0; i < 8; i++) {
        int idx = t + i * 256, m = idx >> 5, g = idx & 31;
        float4 v;
        v.x = Cs[(64 + m) * 133 + 4*g + 0] * ink[4*g + 0];
        v.y = Cs[(64 + m) * 133 + 4*g + 1] * ink[4*g + 1];
        v.z = Cs[(64 + m) * 133 + 4*g + 2] * ink[4*g + 2];
        v.w = Cs[(64 + m) * 133 + 4*g + 3] * ink[4*g + 3];
        *(float4*)(g_Kn + ((size_t)b * M_ + m) * N_ + n0 + 4*g) = v;
        float rs = v.x + v.y + v.z + v.w;
#pragma unroll
        for (int o = 16; o; o >>= 1) rs += __shfl_xor_sync(0xffffffffu, rs, o);
        if (lane == 0) g_Knp[((size_t)b * 32 + blockIdx.x) * M_ + m] = rs;
    }
    // write QnT[n][m]
#pragma unroll
    for (int i = 0; i < 8; i++) {
        int idx = t + i * 256, n = idx >> 4, g = idx & 15;
        float iq = inq[n];
        float4 v;
        v.x = Cs[(4*g + 0) * 133 + n] * iq;
        v.y = Cs[(4*g + 1) * 133 + n] * iq;
        v.z = Cs[(4*g + 2) * 133 + n] * iq;
        v.w = Cs[(4*g + 3) * 133 + n] * iq;
        *(float4*)(g_QnT + ((size_t)b * N_ + n0 + n) * M_ + 4*g) = v;
    }
}

// tiny: fold 32 n-tile partials into Knsum. grid(16), 64 thr
__global__ void rowsum_Kp() {
    int b = blockIdx.x, m = threadIdx.x;
    float s = 0.f;
#pragma unroll
    for (int i = 0; i < 32; i++) s += g_Knp[((size_t)b * 32 + i) * M_ + m];
    g_Knsum[b * M_ + m] = s;
}

// =====================================================================
// kx_mma: D[64m][128c] = Kn @ x^T over k-slice of 1024 (fp16, pipelined).
// Also accumulates per-ksplit xsum partials. grid (4, 16, 4), 256 thr.
// smem: A 0/5120 (2 stages), B 10240/20480 -> 30720; Cs at 0 (33792)
// =====================================================================
#define KX_A(s) ((s) * 5120)
#define KX_B(s) (10240 + (s) * 10240)
#define KX_CS 0
#define KX_BYTES 33792

__global__ __launch_bounds__(256, 1) void kx_mma(const float* __restrict__ x) {
    __shared__ __align__(16) char sm[KX_BYTES];
    const int t = threadIdx.x, lane = t & 31, wid = t >> 5;
    const int b = blockIdx.y, c0 = blockIdx.x * 128, ks = blockIdx.z;
    const float* Kb = g_Kn + (size_t)b * M_ * N_;
    const float* xb = x + (size_t)b * C_ * N_ + (size_t)c0 * N_;
    const int m0 = (wid >> 2) * 32, cw = (wid & 3) * 32;
    const int r = lane >> 2, kq = (lane & 3) * 2;
    float acc[2][4][4] = {};
    float xs[4] = {0.f, 0.f, 0.f, 0.f};

    float4 aR[2], bR[4];
    {   // prologue: load + store step 0
        const int k0 = ks * 1024;
#pragma unroll
        for (int i = 0; i < 2; i++) {
            int idx = t + i * 256, row = idx >> 3, g = idx & 7;
            aR[i] = *(const float4*)(Kb + (size_t)row * N_ + k0 + 4*g);
        }
#pragma unroll
        for (int i = 0; i < 4; i++) {
            int idx = t + i * 256, row = idx >> 3, g = idx & 7;
            bR[i] = *(const float4*)(xb + (size_t)row * N_ + k0 + 4*g);
        }
        __half* Ah = (__half*)(sm + KX_A(0));
        __half* Bh = (__half*)(sm + KX_B(0));
#pragma unroll
        for (int i = 0; i < 2; i++) {
            int idx = t + i * 256, row = idx >> 3, g = idx & 7;
            *(uint2*)(Ah + row * 40 + 4*g) = pk4(aR[i]);
        }
#pragma unroll
        for (int i = 0; i < 4; i++) {
            int idx = t + i * 256, row = idx >> 3, g = idx & 7;
            xs[i] += bR[i].x + bR[i].y + bR[i].z + bR[i].w;
            *(uint2*)(Bh + row * 40 + 4*g) = pk4(bR[i]);
        }
    }
    __syncthreads();

    for (int p = 0; p < 32; ++p) {
        const int s = p & 1;
        if (p < 31) {   // prefetch next step
            const int k0 = ks * 1024 + (p + 1) * 32;
#pragma unroll
            for (int i = 0; i < 2; i++) {
                int idx = t + i * 256, row = idx >> 3, g = idx & 7;
                aR[i] = *(const float4*)(Kb + (size_t)row * N_ + k0 + 4*g);
            }
#pragma unroll
            for (int i = 0; i < 4; i++) {
                int idx = t + i * 256, row = idx >> 3, g = idx & 7;
                bR[i] = *(const float4*)(xb + (size_t)row * N_ + k0 + 4*g);
            }
        }
        {   // mma on current stage
            __half* Ah = (__half*)(sm + KX_A(s));
            __half* Bh = (__half*)(sm + KX_B(s));
#pragma unroll
            for (int kc = 0; kc < 32; kc += 16) {
                uint32_t ah[2][4], bh[4][2];
#pragma unroll
                for (int mf = 0; mf < 2; mf++) ldAf(ah[mf], (char*)Ah, 40, m0 + mf*16, kc, r, kq);
#pragma unroll
                for (int nf = 0; nf < 4; nf++) ldBf(bh[nf], (char*)Bh, 40, cw + nf*8, kc, r, kq);
#pragma unroll
                for (int mf = 0; mf < 2; mf++)
#pragma unroll
                    for (int nf = 0; nf < 4; nf++) mma_f16(acc[mf][nf], ah[mf], bh[nf]);
            }
        }
        if (p < 31) {   // store next stage
            const int sn = (p + 1) & 1;
            __half* Ah = (__half*)(sm + KX_A(sn));
            __half* Bh = (__half*)(sm + KX_B(sn));
#pragma unroll
            for (int i = 0; i < 2; i++) {
                int idx = t + i * 256, row = idx >> 3, g = idx & 7;
                *(uint2*)(Ah + row * 40 + 4*g) = pk4(aR[i]);
            }
#pragma unroll
            for (int i = 0; i < 4; i++) {
                int idx = t + i * 256, row = idx >> 3, g = idx & 7;
                xs[i] += bR[i].x + bR[i].y + bR[i].z + bR[i].w;
                *(uint2*)(Bh + row * 40 + 4*g) = pk4(bR[i]);
            }
        }
        __syncthreads();
    }

    // xsum partial: reduce over 8 column-group threads per row
#pragma unroll
    for (int i = 0; i < 4; i++) {
        float v = xs[i];
        v += __shfl_xor_sync(0xffffffffu, v, 1);
        v += __shfl_xor_sync(0xffffffffu, v, 2);
        v += __shfl_xor_sync(0xffffffffu, v, 4);
        if ((t & 7) == 0)
            g_xsump[ks][b * C_ + c0 + (t >> 3) + 32 * i] = v;
    }

    float* Cs = (float*)(sm + KX_CS);
#pragma unroll
    for (int mf = 0; mf < 2; mf++) {
        int mA = m0 + mf*16 + r, mB = mA + 8;
#pragma unroll
        for (int nf = 0; nf < 4; nf++) {
            int c = cw + nf*8 + kq;
            Cs[mA * 132 + c    ] = acc[mf][nf][0];
            Cs[mA * 132 + c + 1] = acc[mf][nf][1];
            Cs[mB * 132 + c    ] = acc[mf][nf][2];
            Cs[mB * 132 + c + 1] = acc[mf][nf][3];
        }
    }
    __syncthreads();
#pragma unroll
    for (int i = 0; i < 8; i++) {
        int idx = t + i * 256, m = idx >> 5, g = idx & 31;
        float4 v = *(float4*)(Cs + m * 132 + 4*g);
        *(float4*)(g_KXp[ks] + ((size_t)b * M_ + m) * C_ + c0 + 4*g) = v;
    }
}

// =====================================================================
// small fp32 kernels
// =====================================================================
__global__ void vsum_kernel(const float* __restrict__ Wv, const float* __restrict__ bv) {
    int b = blockIdx.y;
    int c = blockIdx.x * 4 + (threadIdx.x >> 5);
    int lane = threadIdx.x & 31;
    const float* w = Wv + (size_t)c * C_;
    float s = 0.f;
    for (int i = lane; i < C_; i += 32) {
        float xsv = g_xsump[0][b * C_ + i] + g_xsump[1][b * C_ + i]
                  + g_xsump[2][b * C_ + i] + g_xsump[3][b * C_ + i];
        s = fmaf(w[i], xsv, s);
    }
#pragma unroll
    for (int o = 16; o; o >>= 1) s += __shfl_xor_sync(0xffffffffu, s, o);
    if (lane == 0) g_Vsum[b * C_ + c] = s + (float)N_ * bv[c];
}

// mat: D[m][c] = sum_k (sum_ks KXp)[m][k] Wv[c][k]; matT[c][m] += bv[c]*Knsum[m]
__global__ void mat_gemm(const float* __restrict__ Wv, const float* __restrict__ bv) {
    __shared__ float As[64][65];
    __shared__ float Bs[64][65];
    int b = blockIdx.y, c0 = blockIdx.x * 64, t = threadIdx.x;
    int tm = t >> 4, tc = t & 15;
    float acc[4][4] = {};
    const float* A0 = g_KXp[0] + (size_t)b * M_ * C_;
    const float* A1 = g_KXp[1] + (size_t)b * M_ * C_;
    const float* A2 = g_KXp[2] + (size_t)b * M_ * C_;
    const float* A3 = g_KXp[3] + (size_t)b * M_ * C_;
    const float* Bm = Wv + (size_t)c0 * C_;
    for (int k0 = 0; k0 < C_; k0 += 64) {
#pragma unroll
        for (int i = 0; i < 16; i++) {
            int idx = t + i * 256, rr = idx >> 6, kk = idx & 63;
            size_t off = (size_t)rr * C_ + k0 + kk;
            As[rr][kk] = A0[off] + A1[off] + A2[off] + A3[off];
            Bs[rr][kk] = Bm[off];
        }
        __syncthreads();
#pragma unroll
        for (int kk = 0; kk < 64; kk++) {
            float a[4], bb[4];
#pragma unroll
            for (int i = 0; i < 4; i++) a[i]  = As[tm + 16*i][kk];
#pragma unroll
            for (int j = 0; j < 4; j++) bb[j] = Bs[tc + 16*j][kk];
#pragma unroll
            for (int i = 0; i < 4; i++)
#pragma unroll
                for (int j = 0; j < 4; j++) acc[i][j] = fmaf(a[i], bb[j], acc[i][j]);
        }
        __syncthreads();
    }
#pragma unroll
    for (int i = 0; i < 4; i++) {
        int m = tm + 16*i;
        float kn = g_Knsum[b * M_ + m];
#pragma unroll
        for (int j = 0; j < 4; j++) {
            int c = c0 + tc + 16*j;
            g_matT[((size_t)b * C_ + c) * M_ + m] = acc[i][j] + bv[c] * kn;
        }
    }
}

// =====================================================================
// final_mma: D[128c][128n] = matT @ QnT^T, K=64, fused tailor.
// grid (32 n, 4 c, 16 b), 256 thr.
// smem: Ah 0 (18432), Bh 18432 -> 36864; Cs 0 (67584); tl 67584, vs 68096,
//       ks 68608 -> 68864
// =====================================================================
#define FN_AH 0
#define FN_BH 18432
#define FN_CS 0
#define FN_TL 67584
#define FN_VS 68096
#define FN_KS 68608
#define FN_BYTES 68864

__global__ __launch_bounds__(256, 1) void final_mma(float* __restrict__ out,
                                                    const float* __restrict__ gamma) {
    extern __shared__ __align__(16) char sm[];
    const int t = threadIdx.x, lane = t & 31, wid = t >> 5;
    const int b = blockIdx.z, c0 = blockIdx.y * 128, n0 = blockIdx.x * 128;
    float* tl = (float*)(sm + FN_TL);
    float* vs = (float*)(sm + FN_VS);
    float* ks = (float*)(sm + FN_KS);
    if (t < 128) vs[t] = g_Vsum[b * C_ + c0 + t];
    if (t < 64)  ks[t] = g_Knsum[b * M_ + t];
    __half* Ah = (__half*)(sm + FN_AH);
    __half* Bh = (__half*)(sm + FN_BH);
#pragma unroll
    for (int i = 0; i < 8; i++) {       // A: matT rows (c), 64 k
        int idx = t + i * 256, row = idx >> 4, g = idx & 15;
        float4 v = *(const float4*)(g_matT + ((size_t)b * C_ + c0 + row) * M_ + 4*g);
        *(uint2*)(Ah + row * 72 + 4*g) = pk4(v);
    }
#pragma unroll
    for (int i = 0; i < 8; i++) {       // B: QnT rows (n), 64 k
        int idx = t + i * 256, row = idx >> 4, g = idx & 15;
        float4 v = *(const float4*)(g_QnT + ((size_t)b * N_ + n0 + row) * M_ + 4*g);
        *(uint2*)(Bh + row * 72 + 4*g) = pk4(v);
    }
    __syncthreads();

    // fused tailor: tl[n] = 1/max(N + Qn[n,:].Knsum, 1e-6)
    if (t < 128) {
        float d = (float)N_;
#pragma unroll
        for (int m = 0; m < 64; m++) d += __half2float(Bh[t * 72 + m]) * ks[m];
        tl[t] = 1.f / fmaxf(d, 1e-6f);
    }

    const int cw = (wid >> 2) * 64, nw = (wid & 3) * 32;
    const int r = lane >> 2, kq = (lane & 3) * 2;
    float acc[4][4][4] = {};
#pragma unroll
    for (int kc = 0; kc < 64; kc += 16) {
        uint32_t ah[4][4], bh[4][2];
#pragma unroll
        for (int mf = 0; mf < 4; mf++) ldAf(ah[mf], (char*)Ah, 72, cw + mf*16, kc, r, kq);
#pragma unroll
        for (int nf = 0; nf < 4; nf++) ldBf(bh[nf], (char*)Bh, 72, nw + nf*8, kc, r, kq);
#pragma unroll
        for (int mf = 0; mf < 4; mf++)
#pragma unroll
            for (int nf = 0; nf < 4; nf++) mma_f16(acc[mf][nf], ah[mf], bh[nf]);
    }
    __syncthreads();

    float* Cs = (float*)(sm + FN_CS);
    float gm = gamma[0];
#pragma unroll
    for (int mf = 0; mf < 4; mf++) {
        int cA = cw + mf*16 + r, cB = cA + 8;
        float vA = vs[cA], vB = vs[cB];
#pragma unroll
        for (int nf = 0; nf < 4; nf++) {
            int n = nw + nf*8 + kq;
            Cs[cA * 132 + n    ] = fixv(gm * tl[n    ] * (vA + acc[mf][nf][0]));
            Cs[cA * 132 + n + 1] = fixv(gm * tl[n + 1] * (vA + acc[mf][nf][1]));
            Cs[cB * 132 + n    ] = fixv(gm * tl[n    ] * (vB + acc[mf][nf][2]));
            Cs[cB * 132 + n + 1] = fixv(gm * tl[n + 1] * (vB + acc[mf][nf][3]));
        }
    }
    __syncthreads();
#pragma unroll
    for (int i = 0; i < 16; i++) {
        int idx = t + i * 256, c = idx >> 5, g = idx & 31;
        float4 v = *(float4*)(Cs + c * 132 + 4*g);
        *(float4*)(out + ((size_t)b * C_ + c0 + c) * N_ + n0 + 4*g) = v;
    }
}

// ---------------------------------------------------------------
extern "C" void kernel_launch(void* const* d_in, const int* in_sizes, int n_in,
                              void* d_out, int out_size) {
    const float* x     = (const float*)d_in[0];
    const float* Wq    = (const float*)d_in[1];
    const float* bq    = (const float*)d_in[2];
    const float* Wk    = (const float*)d_in[3];
    const float* bk    = (const float*)d_in[4];
    const float* Wv    = (const float*)d_in[5];
    const float* bv    = (const float*)d_in[6];
    const float* gamma = (const float*)d_in[7];
    float* out = (float*)d_out;

    cudaFuncSetAttribute(qk_mma,    cudaFuncAttributeMaxDynamicSharedMemorySize, QK_BYTES);
    cudaFuncSetAttribute(final_mma, cudaFuncAttributeMaxDynamicSharedMemorySize, FN_BYTES);

    qk_mma     <<<dim3(32, 16), 256, QK_BYTES>>>(x, Wq, bq, Wk, bk);
    rowsum_Kp  <<<16, 64>>>();
    kx_mma     <<<dim3(4, 16, 4), 256>>>(x);
    vsum_kernel<<<dim3(128, 16), 128>>>(Wv, bv);
    mat_gemm   <<<dim3(8, 16), 256>>>(Wv, bv);
    final_mma  <<<dim3(32, 4, 16), 256, FN_BYTES>>>(out, gamma);
}

// round 7
// speedup vs baseline: 3.2636x; 1.0522x over previous
#include <cuda_runtime.h>
#include <cuda_fp16.h>
#include <cstdint>
#include <math.h>

#define B_ 16
#define C_ 512
#define N_ 4096
#define M_ 64

// ---------------- scratch (static device globals) ----------------
__device__ __align__(128) float g_QnT[B_*N_*M_];      // [b][n][m]
__device__ __align__(128) float g_Kn [B_*M_*N_];      // [b][m][n]
__device__ __align__(128) float g_KXp[4][B_*M_*C_];   // k-split partials
__device__ __align__(128) float g_matT[B_*C_*M_];     // [b][c][m]
__device__ __align__(128) float g_Knp[B_*32*M_];      // Knsum partials per n-tile
__device__ __align__(128) float g_Knsum[B_*M_];
__device__ __align__(128) float g_xsump[4][B_*C_];    // xsum k-split partials
__device__ __align__(128) float g_Vsum[B_*C_];

// ---------------- fp16 pack helpers ----------------
__device__ __forceinline__ uint32_t hpk2(float a, float b) {
    __half2 t = __floats2half2_rn(a, b);
    return *reinterpret_cast<uint32_t*>(&t);
}
__device__ __forceinline__ uint2 pk4(float4 v) {
    uint2 r; r.x = hpk2(v.x, v.y); r.y = hpk2(v.z, v.w); return r;
}
__device__ __forceinline__ uint32_t smem_u32(const void* p) {
    uint32_t a;
    asm("{ .reg .u64 t; cvta.to.shared.u64 t, %1; cvt.u32.u64 %0, t; }" : "=r"(a) : "l"(p));
    return a;
}

// ---------------- mma / ldmatrix helpers ----------------
__device__ __forceinline__ void mma_f16(float c[4], const uint32_t a[4], const uint32_t b[2]) {
    asm volatile("mma.sync.aligned.m16n8k16.row.col.f32.f16.f16.f32 "
        "{%0,%1,%2,%3}, {%4,%5,%6,%7}, {%8,%9}, {%0,%1,%2,%3};"
        : "+f"(c[0]), "+f"(c[1]), "+f"(c[2]), "+f"(c[3])
        : "r"(a[0]), "r"(a[1]), "r"(a[2]), "r"(a[3]), "r"(b[0]), "r"(b[1]));
}
__device__ __forceinline__ void ldsm_x4(uint32_t r[4], uint32_t a) {
    asm volatile("ldmatrix.sync.aligned.m8n8.x4.shared.b16 {%0,%1,%2,%3}, [%4];"
        : "=r"(r[0]), "=r"(r[1]), "=r"(r[2]), "=r"(r[3]) : "r"(a));
}
__device__ __forceinline__ void ldsm_x2(uint32_t r[2], uint32_t a) {
    asm volatile("ldmatrix.sync.aligned.m8n8.x2.shared.b16 {%0,%1}, [%2];"
        : "=r"(r[0]), "=r"(r[1]) : "r"(a));
}
__device__ __forceinline__ void ldsm_x2t(uint32_t r[2], uint32_t a) {
    asm volatile("ldmatrix.sync.aligned.m8n8.x2.trans.shared.b16 {%0,%1}, [%2];"
        : "=r"(r[0]), "=r"(r[1]) : "r"(a));
}
__device__ __forceinline__ float fixv(float v) {
    if (isnan(v)) return 0.f;
    if (isinf(v)) return v > 0.f ? 1.f : -1.f;
    return v;
}

// =====================================================================
// qk_mma: D[128m(64q|64k)][128n] = Wqk @ x, K=512. grid(32,16), 256 thr
// fp16, ldmatrix fragments, B stored k-major + ldmatrix.trans (no staging),
// 1 sync/iter, double-buffered.
// smem: A(s)=s*10240 (128x40 halfs), B(s)=20480+s*8704 (32x136 halfs)
// epilogue Cs at 0 (128*133*4=68096); bias 68096, inq 68608, ink 69120
// =====================================================================
#define QK_A(s)  ((s) * 10240)
#define QK_B(s)  (20480 + (s) * 8704)
#define QK_CS 0
#define QK_BIAS 68096
#define QK_INQ 68608
#define QK_INK 69120
#define QK_BYTES 69632

__global__ __launch_bounds__(256, 1) void qk_mma(
    const float* __restrict__ x,  const float* __restrict__ Wq,
    const float* __restrict__ bq, const float* __restrict__ Wk,
    const float* __restrict__ bk) {
    extern __shared__ __align__(16) char sm[];
    const int t = threadIdx.x, lane = t & 31, wid = t >> 5;
    const int b = blockIdx.y, n0 = blockIdx.x * 128;
    const float* xb = x + (size_t)b * C_ * N_;
    float* bias = (float*)(sm + QK_BIAS);
    float* inq  = (float*)(sm + QK_INQ);
    float* ink  = (float*)(sm + QK_INK);
    if (t < 128) bias[t] = (t < 64) ? bq[t] : bk[t - 64];

    const int m0 = (wid >> 2) * 64, nw = (wid & 3) * 32;
    const int r = lane >> 2, kq = (lane & 3) * 2;
    float acc[4][4][4] = {};

    float4 aR[4], xR[4];
#pragma unroll
    for (int i = 0; i < 4; i++) {
        int idx = t + i * 256, row = idx >> 3, g = idx & 7;
        aR[i] = (row < 64) ? *(const float4*)(Wq + (size_t)row * C_ + 4*g)
                           : *(const float4*)(Wk + (size_t)(row - 64) * C_ + 4*g);
    }
#pragma unroll
    for (int i = 0; i < 4; i++) {
        int idx = t + i * 256, kk = idx >> 5, g = idx & 31;
        xR[i] = *(const float4*)(xb + (size_t)kk * N_ + n0 + 4*g);
    }

    for (int p = 0; p < 16; ++p) {
        const int s = p & 1;
        __half* Ah = (__half*)(sm + QK_A(s));
        __half* Bh = (__half*)(sm + QK_B(s));
#pragma unroll
        for (int i = 0; i < 4; i++) {   // A rows (m), 32 k, pitch 40
            int idx = t + i * 256, row = idx >> 3, g = idx & 7;
            *(uint2*)(Ah + row * 40 + 4*g) = pk4(aR[i]);
        }
#pragma unroll
        for (int i = 0; i < 4; i++) {   // B k-major: 32 k-rows x 128 n, pitch 136
            int idx = t + i * 256, kk = idx >> 5, g = idx & 31;
            *(uint2*)(Bh + kk * 136 + 4*g) = pk4(xR[i]);
        }
        __syncthreads();
        if (p < 15) {   // prefetch next k-step
            const int k0 = (p + 1) * 32;
#pragma unroll
            for (int i = 0; i < 4; i++) {
                int idx = t + i * 256, row = idx >> 3, g = idx & 7;
                aR[i] = (row < 64) ? *(const float4*)(Wq + (size_t)row * C_ + k0 + 4*g)
                                   : *(const float4*)(Wk + (size_t)(row - 64) * C_ + k0 + 4*g);
            }
#pragma unroll
            for (int i = 0; i < 4; i++) {
                int idx = t + i * 256, kk = idx >> 5, g = idx & 31;
                xR[i] = *(const float4*)(xb + (size_t)(k0 + kk) * N_ + n0 + 4*g);
            }
        }
        const uint32_t Ab = smem_u32(Ah), Bb = smem_u32(Bh);
#pragma unroll
        for (int kc = 0; kc < 32; kc += 16) {
            uint32_t ah[4][4], bh[4][2];
#pragma unroll
            for (int mf = 0; mf < 4; mf++)
                ldsm_x4(ah[mf], Ab + ((m0 + mf*16 + (lane & 15)) * 40 + kc + (lane >> 4) * 8) * 2);
#pragma unroll
            for (int nf = 0; nf < 4; nf++)
                ldsm_x2t(bh[nf], Bb + ((kc + (lane & 15)) * 136 + nw + nf*8) * 2);
#pragma unroll
            for (int mf = 0; mf < 4; mf++)
#pragma unroll
                for (int nf = 0; nf < 4; nf++) mma_f16(acc[mf][nf], ah[mf], bh[nf]);
        }
    }
    __syncthreads();   // panels dead; reuse smem as Cs

    float* Cs = (float*)(sm + QK_CS);
#pragma unroll
    for (int mf = 0; mf < 4; mf++) {
        int mA = m0 + mf*16 + r, mB = mA + 8;
        float bA = bias[mA], bB = bias[mB];
#pragma unroll
        for (int nf = 0; nf < 4; nf++) {
            int n = nw + nf*8 + kq;
            Cs[mA * 133 + n    ] = acc[mf][nf][0] + bA;
            Cs[mA * 133 + n + 1] = acc[mf][nf][1] + bA;
            Cs[mB * 133 + n    ] = acc[mf][nf][2] + bB;
            Cs[mB * 133 + n + 1] = acc[mf][nf][3] + bB;
        }
    }
    __syncthreads();
    {   // per-column L2 norms
        int n = t & 127, part = t >> 7, base = part * 64;
        float s = 0.f;
#pragma unroll 8
        for (int m = 0; m < 64; m++) {
            float v = Cs[(base + m) * 133 + n]; s = fmaf(v, v, s);
        }
        float inv = 1.f / fmaxf(sqrtf(s), 1e-6f);
        if (part == 0) inq[n] = inv; else ink[n] = inv;
    }
    __syncthreads();
    // write Kn[m][n] + Knsum partials
#pragma unroll
    for (int i = 0; i < 8; i++) {
        int idx = t + i * 256, m = idx >> 5, g = idx & 31;
        float4 v;
        v.x = Cs[(64 + m) * 133 + 4*g + 0] * ink[4*g + 0];
        v.y = Cs[(64 + m) * 133 + 4*g + 1] * ink[4*g + 1];
        v.z = Cs[(64 + m) * 133 + 4*g + 2] * ink[4*g + 2];
        v.w = Cs[(64 + m) * 133 + 4*g + 3] * ink[4*g + 3];
        *(float4*)(g_Kn + ((size_t)b * M_ + m) * N_ + n0 + 4*g) = v;
        float rs = v.x + v.y + v.z + v.w;
#pragma unroll
        for (int o = 16; o; o >>= 1) rs += __shfl_xor_sync(0xffffffffu, rs, o);
        if (lane == 0) g_Knp[((size_t)b * 32 + blockIdx.x) * M_ + m] = rs;
    }
    // write QnT[n][m]
#pragma unroll
    for (int i = 0; i < 8; i++) {
        int idx = t + i * 256, n = idx >> 4, g = idx & 15;
        float iq = inq[n];
        float4 v;
        v.x = Cs[(4*g + 0) * 133 + n] * iq;
        v.y = Cs[(4*g + 1) * 133 + n] * iq;
        v.z = Cs[(4*g + 2) * 133 + n] * iq;
        v.w = Cs[(4*g + 3) * 133 + n] * iq;
        *(float4*)(g_QnT + ((size_t)b * N_ + n0 + n) * M_ + 4*g) = v;
    }
}

// tiny: fold 32 n-tile partials into Knsum. grid(16), 64 thr
__global__ void rowsum_Kp() {
    int b = blockIdx.x, m = threadIdx.x;
    float s = 0.f;
#pragma unroll
    for (int i = 0; i < 32; i++) s += g_Knp[((size_t)b * 32 + i) * M_ + m];
    g_Knsum[b * M_ + m] = s;
}

// =====================================================================
// kx_mma: D[64m][128c] = Kn @ x^T over k-slice of 1024 (fp16, ldmatrix).
// grid (4, 16, 4), 256 thr, 1 sync/iter. smem: A(s)=s*5120 (64x40),
// B(s)=10240+s*10240 (128x40); Cs at 0 (33792)
// =====================================================================
#define KX_A(s) ((s) * 5120)
#define KX_B(s) (10240 + (s) * 10240)
#define KX_CS 0
#define KX_BYTES 33792

__global__ __launch_bounds__(256, 1) void kx_mma(const float* __restrict__ x) {
    __shared__ __align__(16) char sm[KX_BYTES];
    const int t = threadIdx.x, lane = t & 31, wid = t >> 5;
    const int b = blockIdx.y, c0 = blockIdx.x * 128, ks = blockIdx.z;
    const float* Kb = g_Kn + (size_t)b * M_ * N_;
    const float* xb = x + (size_t)b * C_ * N_ + (size_t)c0 * N_;
    const int m0 = (wid >> 2) * 32, cw = (wid & 3) * 32;
    const int r = lane >> 2, kq = (lane & 3) * 2;
    float acc[2][4][4] = {};
    float xs[4] = {0.f, 0.f, 0.f, 0.f};

    float4 aR[2], bR[4];
    {   // prologue: load step 0
        const int k0 = ks * 1024;
#pragma unroll
        for (int i = 0; i < 2; i++) {
            int idx = t + i * 256, row = idx >> 3, g = idx & 7;
            aR[i] = *(const float4*)(Kb + (size_t)row * N_ + k0 + 4*g);
        }
#pragma unroll
        for (int i = 0; i < 4; i++) {
            int idx = t + i * 256, row = idx >> 3, g = idx & 7;
            bR[i] = *(const float4*)(xb + (size_t)row * N_ + k0 + 4*g);
        }
    }

    for (int p = 0; p < 32; ++p) {
        const int s = p & 1;
        __half* Ah = (__half*)(sm + KX_A(s));
        __half* Bh = (__half*)(sm + KX_B(s));
#pragma unroll
        for (int i = 0; i < 2; i++) {
            int idx = t + i * 256, row = idx >> 3, g = idx & 7;
            *(uint2*)(Ah + row * 40 + 4*g) = pk4(aR[i]);
        }
#pragma unroll
        for (int i = 0; i < 4; i++) {
            int idx = t + i * 256, row = idx >> 3, g = idx & 7;
            xs[i] += bR[i].x + bR[i].y + bR[i].z + bR[i].w;
            *(uint2*)(Bh + row * 40 + 4*g) = pk4(bR[i]);
        }
        __syncthreads();
        if (p < 31) {   // prefetch next step
            const int k0 = ks * 1024 + (p + 1) * 32;
#pragma unroll
            for (int i = 0; i < 2; i++) {
                int idx = t + i * 256, row = idx >> 3, g = idx & 7;
                aR[i] = *(const float4*)(Kb + (size_t)row * N_ + k0 + 4*g);
            }
#pragma unroll
            for (int i = 0; i < 4; i++) {
                int idx = t + i * 256, row = idx >> 3, g = idx & 7;
                bR[i] = *(const float4*)(xb + (size_t)row * N_ + k0 + 4*g);
            }
        }
        const uint32_t Ab = smem_u32(Ah), Bb = smem_u32(Bh);
#pragma unroll
        for (int kc = 0; kc < 32; kc += 16) {
            uint32_t ah[2][4], bh[4][2];
#pragma unroll
            for (int mf = 0; mf < 2; mf++)
                ldsm_x4(ah[mf], Ab + ((m0 + mf*16 + (lane & 15)) * 40 + kc + (lane >> 4) * 8) * 2);
#pragma unroll
            for (int nf = 0; nf < 4; nf++)
                ldsm_x2(bh[nf], Bb + ((cw + nf*8 + (lane & 7)) * 40 + kc + ((lane >> 3) & 1) * 8) * 2);
#pragma unroll
            for (int mf = 0; mf < 2; mf++)
#pragma unroll
                for (int nf = 0; nf < 4; nf++) mma_f16(acc[mf][nf], ah[mf], bh[nf]);
        }
    }

    // xsum partial: reduce over 8 column-group threads per row
#pragma unroll
    for (int i = 0; i < 4; i++) {
        float v = xs[i];
        v += __shfl_xor_sync(0xffffffffu, v, 1);
        v += __shfl_xor_sync(0xffffffffu, v, 2);
        v += __shfl_xor_sync(0xffffffffu, v, 4);
        if ((t & 7) == 0)
            g_xsump[ks][b * C_ + c0 + (t >> 3) + 32 * i] = v;
    }
    __syncthreads();

    float* Cs = (float*)(sm + KX_CS);
#pragma unroll
    for (int mf = 0; mf < 2; mf++) {
        int mA = m0 + mf*16 + r, mB = mA + 8;
#pragma unroll
        for (int nf = 0; nf < 4; nf++) {
            int c = cw + nf*8 + kq;
            Cs[mA * 132 + c    ] = acc[mf][nf][0];
            Cs[mA * 132 + c + 1] = acc[mf][nf][1];
            Cs[mB * 132 + c    ] = acc[mf][nf][2];
            Cs[mB * 132 + c + 1] = acc[mf][nf][3];
        }
    }
    __syncthreads();
#pragma unroll
    for (int i = 0; i < 8; i++) {
        int idx = t + i * 256, m = idx >> 5, g = idx & 31;
        float4 v = *(float4*)(Cs + m * 132 + 4*g);
        *(float4*)(g_KXp[ks] + ((size_t)b * M_ + m) * C_ + c0 + 4*g) = v;
    }
}

// =====================================================================
// vsum: Vsum[b][c] = Wv[c,:].xsum[b,:] + N*bv[c]. grid(32), 256 thr.
// Wv chunk + folded xsum staged to smem once; pure-smem dots after.
// =====================================================================
#define VS_BYTES (32768 + 32768)
__global__ __launch_bounds__(256, 1) void vsum_kernel(const float* __restrict__ Wv,
                                                      const float* __restrict__ bv) {
    extern __shared__ __align__(16) float vsm[];
    float* wv = vsm;             // 16 c x 512
    float* xss = vsm + 16 * 512; // 16 b x 512
    const int t = threadIdx.x, c0 = blockIdx.x * 16;
#pragma unroll
    for (int i = 0; i < 8; i++) {   // Wv chunk, float4
        int idx = t + i * 256, row = idx >> 7, g = idx & 127;
        *(float4*)(wv + row * 512 + 4*g) = *(const float4*)(Wv + (size_t)(c0 + row) * C_ + 4*g);
    }
#pragma unroll
    for (int i = 0; i < 32; i++) {  // folded xsum
        int idx = t + i * 256;
        xss[idx] = g_xsump[0][idx] + g_xsump[1][idx] + g_xsump[2][idx] + g_xsump[3][idx];
    }
    __syncthreads();
    const int cl = t >> 4, kseg = t & 15;
    float bvv = bv[c0 + cl];
    for (int b = 0; b < 16; b++) {
        float s = 0.f;
#pragma unroll
        for (int ii = 0; ii < 32; ii++) {
            int kk = kseg + 16 * ii;
            s = fmaf(wv[cl * 512 + kk], xss[b * 512 + kk], s);
        }
        s += __shfl_xor_sync(0xffffffffu, s, 1);
        s += __shfl_xor_sync(0xffffffffu, s, 2);
        s += __shfl_xor_sync(0xffffffffu, s, 4);
        s += __shfl_xor_sync(0xffffffffu, s, 8);
        if (kseg == 0) g_Vsum[b * C_ + c0 + cl] = s + (float)N_ * bvv;
    }
}

// mat: D[m][c] = sum_k (sum_ks KXp)[m][k] Wv[c][k]; matT[c][m] += bv[c]*Knsum[m]
__global__ void mat_gemm(const float* __restrict__ Wv, const float* __restrict__ bv) {
    __shared__ float As[64][65];
    __shared__ float Bs[64][65];
    int b = blockIdx.y, c0 = blockIdx.x * 64, t = threadIdx.x;
    int tm = t >> 4, tc = t & 15;
    float acc[4][4] = {};
    const float* A0 = g_KXp[0] + (size_t)b * M_ * C_;
    const float* A1 = g_KXp[1] + (size_t)b * M_ * C_;
    const float* A2 = g_KXp[2] + (size_t)b * M_ * C_;
    const float* A3 = g_KXp[3] + (size_t)b * M_ * C_;
    const float* Bm = Wv + (size_t)c0 * C_;
    for (int k0 = 0; k0 < C_; k0 += 64) {
#pragma unroll
        for (int i = 0; i < 16; i++) {
            int idx = t + i * 256, rr = idx >> 6, kk = idx & 63;
            size_t off = (size_t)rr * C_ + k0 + kk;
            As[rr][kk] = A0[off] + A1[off] + A2[off] + A3[off];
            Bs[rr][kk] = Bm[off];
        }
        __syncthreads();
#pragma unroll
        for (int kk = 0; kk < 64; kk++) {
            float a[4], bb[4];
#pragma unroll
            for (int i = 0; i < 4; i++) a[i]  = As[tm + 16*i][kk];
#pragma unroll
            for (int j = 0; j < 4; j++) bb[j] = Bs[tc + 16*j][kk];
#pragma unroll
            for (int i = 0; i < 4; i++)
#pragma unroll
                for (int j = 0; j < 4; j++) acc[i][j] = fmaf(a[i], bb[j], acc[i][j]);
        }
        __syncthreads();
    }
#pragma unroll
    for (int i = 0; i < 4; i++) {
        int m = tm + 16*i;
        float kn = g_Knsum[b * M_ + m];
#pragma unroll
        for (int j = 0; j < 4; j++) {
            int c = c0 + tc + 16*j;
            g_matT[((size_t)b * C_ + c) * M_ + m] = acc[i][j] + bv[c] * kn;
        }
    }
}

// =====================================================================
// final_mma: D[128c][128n] = matT @ QnT^T, K=64, fused tailor, ldmatrix.
// grid (32 n, 4 c, 16 b), 256 thr.
// smem: Ah 0 (128x72 halfs), Bh 18432 -> 36864; Cs 0 (67584); tl 67584,
//       vs 68096, ks 68608 -> 68864
// =====================================================================
#define FN_AH 0
#define FN_BH 18432
#define FN_CS 0
#define FN_TL 67584
#define FN_VS 68096
#define FN_KS 68608
#define FN_BYTES 68864

__global__ __launch_bounds__(256, 1) void final_mma(float* __restrict__ out,
                                                    const float* __restrict__ gamma) {
    extern __shared__ __align__(16) char sm[];
    const int t = threadIdx.x, lane = t & 31, wid = t >> 5;
    const int b = blockIdx.z, c0 = blockIdx.y * 128, n0 = blockIdx.x * 128;
    float* tl = (float*)(sm + FN_TL);
    float* vs = (float*)(sm + FN_VS);
    float* ks = (float*)(sm + FN_KS);
    if (t < 128) vs[t] = g_Vsum[b * C_ + c0 + t];
    if (t < 64)  ks[t] = g_Knsum[b * M_ + t];
    __half* Ah = (__half*)(sm + FN_AH);
    __half* Bh = (__half*)(sm + FN_BH);
#pragma unroll
    for (int i = 0; i < 8; i++) {       // A: matT rows (c), 64 k
        int idx = t + i * 256, row = idx >> 4, g = idx & 15;
        float4 v = *(const float4*)(g_matT + ((size_t)b * C_ + c0 + row) * M_ + 4*g);
        *(uint2*)(Ah + row * 72 + 4*g) = pk4(v);
    }
#pragma unroll
    for (int i = 0; i < 8; i++) {       // B: QnT rows (n), 64 k
        int idx = t + i * 256, row = idx >> 4, g = idx & 15;
        float4 v = *(const float4*)(g_QnT + ((size_t)b * N_ + n0 + row) * M_ + 4*g);
        *(uint2*)(Bh + row * 72 + 4*g) = pk4(v);
    }
    __syncthreads();

    // fused tailor: tl[n] = 1/max(N + Qn[n,:].Knsum, 1e-6)
    if (t < 128) {
        float d = (float)N_;
#pragma unroll
        for (int m = 0; m < 64; m++) d += __half2float(Bh[t * 72 + m]) * ks[m];
        tl[t] = 1.f / fmaxf(d, 1e-6f);
    }

    const int cw = (wid >> 2) * 64, nw = (wid & 3) * 32;
    const int r = lane >> 2, kq = (lane & 3) * 2;
    const uint32_t Ab = smem_u32(Ah), Bb = smem_u32(Bh);
    float acc[4][4][4] = {};
#pragma unroll
    for (int kc = 0; kc < 64; kc += 16) {
        uint32_t ah[4][4], bh[4][2];
#pragma unroll
        for (int mf = 0; mf < 4; mf++)
            ldsm_x4(ah[mf], Ab + ((cw + mf*16 + (lane & 15)) * 72 + kc + (lane >> 4) * 8) * 2);
#pragma unroll
        for (int nf = 0; nf < 4; nf++)
            ldsm_x2(bh[nf], Bb + ((nw + nf*8 + (lane & 7)) * 72 + kc + ((lane >> 3) & 1) * 8) * 2);
#pragma unroll
        for (int mf = 0; mf < 4; mf++)
#pragma unroll
            for (int nf = 0; nf < 4; nf++) mma_f16(acc[mf][nf], ah[mf], bh[nf]);
    }
    __syncthreads();

    float* Cs = (float*)(sm + FN_CS);
    float gm = gamma[0];
#pragma unroll
    for (int mf = 0; mf < 4; mf++) {
        int cA = cw + mf*16 + r, cB = cA + 8;
        float vA = vs[cA], vB = vs[cB];
#pragma unroll
        for (int nf = 0; nf < 4; nf++) {
            int n = nw + nf*8 + kq;
            Cs[cA * 132 + n    ] = fixv(gm * tl[n    ] * (vA + acc[mf][nf][0]));
            Cs[cA * 132 + n + 1] = fixv(gm * tl[n + 1] * (vA + acc[mf][nf][1]));
            Cs[cB * 132 + n    ] = fixv(gm * tl[n    ] * (vB + acc[mf][nf][2]));
            Cs[cB * 132 + n + 1] = fixv(gm * tl[n + 1] * (vB + acc[mf][nf][3]));
        }
    }
    __syncthreads();
#pragma unroll
    for (int i = 0; i < 16; i++) {
        int idx = t + i * 256, c = idx >> 5, g = idx & 31;
        float4 v = *(float4*)(Cs + c * 132 + 4*g);
        *(float4*)(out + ((size_t)b * C_ + c0 + c) * N_ + n0 + 4*g) = v;
    }
}

// ---------------------------------------------------------------
extern "C" void kernel_launch(void* const* d_in, const int* in_sizes, int n_in,
                              void* d_out, int out_size) {
    const float* x     = (const float*)d_in[0];
    const float* Wq    = (const float*)d_in[1];
    const float* bq    = (const float*)d_in[2];
    const float* Wk    = (const float*)d_in[3];
    const float* bk    = (const float*)d_in[4];
    const float* Wv    = (const float*)d_in[5];
    const float* bv    = (const float*)d_in[6];
    const float* gamma = (const float*)d_in[7];
    float* out = (float*)d_out;

    cudaFuncSetAttribute(qk_mma,      cudaFuncAttributeMaxDynamicSharedMemorySize, QK_BYTES);
    cudaFuncSetAttribute(vsum_kernel, cudaFuncAttributeMaxDynamicSharedMemorySize, VS_BYTES);
    cudaFuncSetAttribute(final_mma,   cudaFuncAttributeMaxDynamicSharedMemorySize, FN_BYTES);

    qk_mma     <<<dim3(32, 16), 256, QK_BYTES>>>(x, Wq, bq, Wk, bk);
    rowsum_Kp  <<<16, 64>>>();
    kx_mma     <<<dim3(4, 16, 4), 256>>>(x);
    vsum_kernel<<<32, 256, VS_BYTES>>>(Wv, bv);
    mat_gemm   <<<dim3(8, 16), 256>>>(Wv, bv);
    final_mma  <<<dim3(32, 4, 16), 256, FN_BYTES>>>(out, gamma);
}